// round 10
// baseline (speedup 1.0000x reference)
#include <cuda_runtime.h>
#include <cuda_bf16.h>
#include <math.h>
#include <stdint.h>

// ---------------------------------------------------------------------------
// CAT_Attention (B=1, BLOCK=2048, CHUNK=64, DIM=1024, CAT=1024, NH=16, HD=64)
// S = 2081, W = 65, NC = 32
// Round 10: comp v4 (2-deep W prefetch, 2-stage smem, 1 sync/iter);
// BM=64 GEMM variant for the small-grid dense GEMMs (expand/o/final).
// ---------------------------------------------------------------------------

#define S_LEN   2081
#define CATD    1024
#define NHEAD   16
#define CSLICES 64

typedef __nv_bfloat16 bf16;
typedef __nv_bfloat162 bf162;

// -------------------- scratch (device globals; no allocs) -------------------
__device__ float g_fxpart[CSLICES * 32 * 1024];
__device__ float g_qkv [S_LEN * 3 * CATD];
__device__ bf16  g_xhi[2048 * 1024],  g_xlo[2048 * 1024];
__device__ bf16  g_hhi[S_LEN * 1024], g_hlo[S_LEN * 1024];
__device__ bf16  g_yhi[S_LEN * 1024], g_ylo[S_LEN * 1024];
__device__ bf16  g_y2hi[S_LEN * 1024], g_y2lo[S_LEN * 1024];
__device__ bf16  g_wexphi[1024 * 1024], g_wexplo[1024 * 1024];
__device__ bf16  g_wqkvhi[1024 * 3072], g_wqkvlo[1024 * 3072];
__device__ bf16  g_wohi[1024 * 1024],   g_wolo[1024 * 1024];
__device__ bf16  g_wfinhi[1024 * 1024], g_wfinlo[1024 * 1024];

// -------------------- row maps ---------------------------------------------
__device__ __forceinline__ int amap_final(int r) {
    if (r < 63)    return r + 1;
    if (r == 2047) return 2080;
    int u = r - 63;
    return 65 + u + (u >> 6);
}

// -------------------- helpers ----------------------------------------------
__device__ __forceinline__ uint32_t smem_u32(const void* p) {
    return (uint32_t)__cvta_generic_to_shared(p);
}

__device__ __forceinline__ void cp16(uint32_t dst, const void* src) {
    asm volatile("cp.async.cg.shared.global [%0], [%1], 16;\n" :: "r"(dst), "l"(src));
}

__device__ __forceinline__ void mma16816(float* c, const uint32_t* a, const uint32_t* b) {
    asm volatile(
        "mma.sync.aligned.m16n8k16.row.col.f32.bf16.bf16.f32 "
        "{%0,%1,%2,%3}, {%4,%5,%6,%7}, {%8,%9}, {%0,%1,%2,%3};"
        : "+f"(c[0]), "+f"(c[1]), "+f"(c[2]), "+f"(c[3])
        : "r"(a[0]), "r"(a[1]), "r"(a[2]), "r"(a[3]), "r"(b[0]), "r"(b[1]));
}

__device__ __forceinline__ void ldmat4(uint32_t* r, uint32_t addr) {
    asm volatile(
        "ldmatrix.sync.aligned.m8n8.x4.shared.b16 {%0,%1,%2,%3}, [%4];"
        : "=r"(r[0]), "=r"(r[1]), "=r"(r[2]), "=r"(r[3]) : "r"(addr));
}

__device__ __forceinline__ void ldmat4t(uint32_t* r, uint32_t addr) {
    asm volatile(
        "ldmatrix.sync.aligned.m8n8.x4.trans.shared.b16 {%0,%1,%2,%3}, [%4];"
        : "=r"(r[0]), "=r"(r[1]), "=r"(r[2]), "=r"(r[3]) : "r"(addr));
}

__device__ __forceinline__ void split2(float a, float b, uint32_t& hi, uint32_t& lo) {
    bf16 h0 = __float2bfloat16(a), h1 = __float2bfloat16(b);
    bf16 l0 = __float2bfloat16(a - __bfloat162float(h0));
    bf16 l1 = __float2bfloat16(b - __bfloat162float(h1));
    bf162 hh = __halves2bfloat162(h0, h1), ll = __halves2bfloat162(l0, l1);
    hi = *(uint32_t*)&hh; lo = *(uint32_t*)&ll;
}

__device__ __forceinline__ void st_bf16pair(bf16* hi, bf16* lo, size_t idx,
                                            float v0, float v1) {
    uint32_t h, l;
    split2(v0, v1, h, l);
    *(uint32_t*)(hi + idx) = h;
    *(uint32_t*)(lo + idx) = l;
}

// ---------------------------------------------------------------------------
// convert fp32 -> bf16 hi/lo
// ---------------------------------------------------------------------------
__global__ void cvt_kernel(const float* __restrict__ src, bf16* __restrict__ hi,
                           bf16* __restrict__ lo, int n4)
{
    int i = blockIdx.x * blockDim.x + threadIdx.x;
    if (i >= n4) return;
    float4 v = ((const float4*)src)[i];
    uint2 uh, ul;
    split2(v.x, v.y, uh.x, ul.x);
    split2(v.z, v.w, uh.y, ul.y);
    *(uint2*)(hi + 4 * (size_t)i) = uh;
    *(uint2*)(lo + 4 * (size_t)i) = ul;
}

// ---------------------------------------------------------------------------
// GEMM engine v3.2: templated block-M (BM=128: 256thr 8 warps; BM=64: 128thr
// 4 warps). XOR-swizzled smem, 3-stage cp.async, 1 sync/iter, term-major.
// Warp tile 32x64 in both cases.
// AMODE: 0 identity, 1 gather amap_final.
// CMODE: 0 fp32 C, 1 bf16 scatter->h, 2 bf16 identity, 3 fp32 + fused RoPE.
// Stage layout: Ahi@0 Alo@ASZ Bhi@2*ASZ Blo@2*ASZ+8192; ASZ = BM*64.
// ---------------------------------------------------------------------------
template<int AMODE, int CMODE, int BM>
__global__ __launch_bounds__(BM * 2, BM == 128 ? 2 : 3)
void mma_gemm(const bf16* __restrict__ Agh, const bf16* __restrict__ Agl,
              const bf16* __restrict__ Bgh, const bf16* __restrict__ Bgl,
              float* __restrict__ C, bf16* __restrict__ Chi, bf16* __restrict__ Clo,
              const float* __restrict__ cosb, const float* __restrict__ sinb,
              int M, int N, int K)
{
    constexpr int NT = BM * 2;                 // threads
    constexpr uint32_t ASZ = (uint32_t)BM * 64u;
    constexpr uint32_t STG = 2u * ASZ + 16384u;
    constexpr int BPASS = 512 / NT;            // B chunk passes per thread (2 or 4)
    constexpr int BROWS = NT / 16;             // B rows per pass (16 or 8)

    extern __shared__ char dsm[];
    const uint32_t sb = smem_u32(dsm);
    const int tid = threadIdx.x, lane = tid & 31, wid = tid >> 5;
    const int warp_m = wid & (BM / 32 - 1), warp_n = wid / (BM / 32);
    const int bm = blockIdx.y * BM, bn = blockIdx.x * 128;

    // ---- cp.async source/dest (swizzled) ----
    size_t aoff[2];
#pragma unroll
    for (int i = 0; i < 2; i++) {
        int gr = bm + (tid >> 2) + i * (BM / 2);
        int r = (gr < M) ? gr : 0;
        if (AMODE == 1) r = amap_final(r);
        aoff[i] = (size_t)r * K + (tid & 3) * 8;
    }
    const int arow0 = tid >> 2;
    const uint32_t aswz = (uint32_t)(((tid & 3) ^ ((arow0 >> 1) & 3)) << 4);
    uint32_t a_dst[2];
#pragma unroll
    for (int i = 0; i < 2; i++) a_dst[i] = (uint32_t)((arow0 + i * (BM / 2)) * 64) + aswz;

    const int krow0 = tid >> 4;
    const size_t b_col = (size_t)bn + (tid & 15) * 8;
    const uint32_t bswz = (uint32_t)((((tid & 15) ^ (krow0 & 7))) << 4);
    uint32_t b_dst[BPASS];
#pragma unroll
    for (int i = 0; i < BPASS; i++) b_dst[i] = (uint32_t)((krow0 + i * BROWS) * 256) + bswz;

    // ---- ldmatrix addressing ----
    const int quad = lane >> 3, lrow = lane & 7;
    const int c2 = quad >> 1;
    const int rowLocal = (quad & 1) * 8 + lrow;
    const uint32_t aRowByte = (uint32_t)((warp_m * 32 + rowLocal) * 64);
    const int swA = (rowLocal >> 1) & 3;
    const uint32_t bRowByte = (uint32_t)(rowLocal * 256);

    float acc[16][4];
#pragma unroll
    for (int i = 0; i < 16; i++)
#pragma unroll
        for (int j = 0; j < 4; j++) acc[i][j] = 0.f;

    const int NIT = K >> 5;

    auto issue = [&](int it) {
        const int k0 = it << 5;
        const uint32_t st = sb + (uint32_t)(it % 3) * STG;
#pragma unroll
        for (int i = 0; i < 2; i++) {
            cp16(st + a_dst[i],       Agh + aoff[i] + k0);
            cp16(st + ASZ + a_dst[i], Agl + aoff[i] + k0);
        }
#pragma unroll
        for (int i = 0; i < BPASS; i++) {
            size_t src = (size_t)(k0 + krow0 + i * BROWS) * N + b_col;
            cp16(st + 2u * ASZ + b_dst[i],          Bgh + src);
            cp16(st + 2u * ASZ + 8192u + b_dst[i],  Bgl + src);
        }
        asm volatile("cp.async.commit_group;\n" ::: "memory");
    };

    issue(0);
    issue(1);
    for (int it = 0; it < NIT; it++) {
        if (it + 1 < NIT)
            asm volatile("cp.async.wait_group 1;\n" ::: "memory");
        else
            asm volatile("cp.async.wait_group 0;\n" ::: "memory");
        __syncthreads();
        if (it + 2 < NIT) issue(it + 2);

        const uint32_t st = sb + (uint32_t)(it % 3) * STG;
#pragma unroll
        for (int kk = 0; kk < 2; kk++) {
            uint32_t ah[2][4], al[2][4];
#pragma unroll
            for (int mf = 0; mf < 2; mf++) {
                uint32_t achunk = (uint32_t)((((kk * 2 + c2) ^ swA)) << 4);
                uint32_t aaddr = st + aRowByte + (uint32_t)(mf * 1024) + achunk;
                ldmat4(ah[mf], aaddr);
                ldmat4(al[mf], aaddr + ASZ);
            }
            const uint32_t bk = st + 2u * ASZ + (uint32_t)(kk * 16 * 256) + bRowByte;
#pragma unroll
            for (int j = 0; j < 4; j++) {
                uint32_t bh[4], bl[4];
                uint32_t bchunk = (uint32_t)(((warp_n * 8 + c2 + j * 2) ^ lrow) << 4);
                ldmat4t(bh, bk + bchunk);
                ldmat4t(bl, bk + bchunk + 8192u);
#pragma unroll
                for (int h = 0; h < 2; h++)
#pragma unroll
                    for (int mf = 0; mf < 2; mf++)
                        mma16816(acc[mf * 8 + j * 2 + h], ah[mf], &bh[h * 2]);
#pragma unroll
                for (int h = 0; h < 2; h++)
#pragma unroll
                    for (int mf = 0; mf < 2; mf++)
                        mma16816(acc[mf * 8 + j * 2 + h], ah[mf], &bl[h * 2]);
#pragma unroll
                for (int h = 0; h < 2; h++)
#pragma unroll
                    for (int mf = 0; mf < 2; mf++)
                        mma16816(acc[mf * 8 + j * 2 + h], al[mf], &bh[h * 2]);
            }
        }
    }

    // ---- epilogue ----
    const int ra = lane >> 2, ka = lane & 3;
    const int colBase = bn + warp_n * 64;

    if (CMODE == 3 && colBase < 2048) {
#pragma unroll
        for (int mf = 0; mf < 2; mf++)
#pragma unroll
            for (int hh = 0; hh < 2; hh++) {
                int gr = bm + warp_m * 32 + mf * 16 + ra + hh * 8;
                if (gr >= M) continue;
                const float* cb = cosb + (size_t)gr * 64;
                const float* sn = sinb + (size_t)gr * 64;
#pragma unroll
                for (int nf = 0; nf < 4; nf++) {
                    int d = nf * 8 + ka * 2;
                    float a0 = acc[mf * 8 + nf][hh * 2];
                    float a1 = acc[mf * 8 + nf][hh * 2 + 1];
                    float b0 = acc[mf * 8 + nf + 4][hh * 2];
                    float b1 = acc[mf * 8 + nf + 4][hh * 2 + 1];
                    float o0 = a0 * cb[d]     - b0 * sn[d];
                    float o1 = a1 * cb[d + 1] - b1 * sn[d + 1];
                    float p0 = b0 * cb[d + 32] + a0 * sn[d + 32];
                    float p1 = b1 * cb[d + 33] + a1 * sn[d + 33];
                    *(float2*)&C[(size_t)gr * N + colBase + d]      = make_float2(o0, o1);
                    *(float2*)&C[(size_t)gr * N + colBase + d + 32] = make_float2(p0, p1);
                }
            }
        return;
    }

#pragma unroll
    for (int mf = 0; mf < 2; mf++)
#pragma unroll
        for (int nf = 0; nf < 8; nf++) {
            const float* c = acc[mf * 8 + nf];
            int col = colBase + nf * 8 + ka * 2;
#pragma unroll
            for (int h = 0; h < 2; h++) {
                int gr = bm + warp_m * 32 + mf * 16 + ra + h * 8;
                if (gr >= M) continue;
                float v0 = c[h * 2], v1 = c[h * 2 + 1];
                if (CMODE == 0 || CMODE == 3) {
                    *(float2*)&C[(size_t)gr * N + col] = make_float2(v0, v1);
                } else {
                    int cr = (CMODE == 1) ? ((gr >> 6) * 65 + 1 + (gr & 63)) : gr;
                    st_bf16pair(Chi, Clo, (size_t)cr * N + col, v0, v1);
                }
            }
        }
}

#define DSMEM128 98304
#define DSMEM64  73728

// ---------------------------------------------------------------------------
// comp GEMM v4: fx = x.reshape(32,65536) @ W_comp, split-K.
// 2-deep register prefetch of W/x, 2-stage smem, ONE sync per iteration.
// grid (8 N-tiles, 64 K-slices), 256 threads.
// ---------------------------------------------------------------------------
__global__ __launch_bounds__(256, 2)
void comp_kernel(const bf16* __restrict__ xhi, const bf16* __restrict__ xlo,
                 const float* __restrict__ Wc, float* __restrict__ fxpart)
{
    __shared__ bf16 Ahi[2][32][40], Alo[2][32][40];
    __shared__ bf16 Bhi[2][32][136], Blo[2][32][136];

    const int tid = threadIdx.x, lane = tid & 31, warp = tid >> 5;
    const int bn = blockIdx.x * 128;
    const int kb = blockIdx.y * 1024;

    const int wr = tid >> 3, wc = (tid & 7) * 16;   // W: 32 rows x 8x16 cols
    const int xr = tid >> 3, xc = (tid & 7) * 4;    // x: 32 rows x 8x4 cols

    float4 wreg[2][4];
    uint2 xh[2], xl[2];
    auto loadTo = [&](int slot, int k0) {
        const float* wp = Wc + (size_t)(kb + k0 + wr) * 1024 + bn + wc;
#pragma unroll
        for (int i = 0; i < 4; i++) wreg[slot][i] = *(const float4*)(wp + i * 4);
        size_t xoff = (size_t)xr * 65536 + kb + k0 + xc;
        xh[slot] = *(const uint2*)(xhi + xoff);
        xl[slot] = *(const uint2*)(xlo + xoff);
    };

    float acc[2][2][4];
#pragma unroll
    for (int i = 0; i < 2; i++)
#pragma unroll
        for (int j = 0; j < 2; j++)
#pragma unroll
            for (int q = 0; q < 4; q++) acc[i][j][q] = 0.f;

    const uint32_t ah_base = smem_u32(&Ahi[0][0][0]);
    const uint32_t al_base = smem_u32(&Alo[0][0][0]);
    const uint32_t bh_base = smem_u32(&Bhi[0][0][0]);
    const uint32_t bl_base = smem_u32(&Blo[0][0][0]);
    const int quad = lane >> 3, lrow = lane & 7;
    const uint32_t a_off = (uint32_t)(((quad & 1) * 8 + lrow) * 80 + (quad >> 1) * 16);
    const uint32_t b_off = (uint32_t)(((quad & 1) * 8 + lrow) * 272 + (warp * 16 + (quad >> 1) * 8) * 2);

    loadTo(0, 0);
    loadTo(1, 32);

    for (int it = 0; it < 32; it++) {
        const int s = it & 1;
        // stage-s WAR: all warps finished mma on stage s (iter it-2) before
        // passing sync(it-1); our STS here follows that sync.
#pragma unroll
        for (int i = 0; i < 4; i++) {
            float4 v = wreg[s][i];
            uint2 uh, ul;
            split2(v.x, v.y, uh.x, ul.x);
            split2(v.z, v.w, uh.y, ul.y);
            *(uint2*)&Bhi[s][wr][wc + i * 4] = uh;
            *(uint2*)&Blo[s][wr][wc + i * 4] = ul;
        }
        *(uint2*)&Ahi[s][xr][xc] = xh[s];
        *(uint2*)&Alo[s][xr][xc] = xl[s];

        if (it + 2 < 32) loadTo(s, (it + 2) * 32);
        __syncthreads();

        const uint32_t as = ah_base + (uint32_t)s * 2560u;
        const uint32_t ls = al_base + (uint32_t)s * 2560u;
        const uint32_t bs = bh_base + (uint32_t)s * 8704u;
        const uint32_t cs = bl_base + (uint32_t)s * 8704u;
#pragma unroll
        for (int kk = 0; kk < 2; kk++) {
            uint32_t ah[2][4], al[2][4], bh[4], bl[4];
#pragma unroll
            for (int mf = 0; mf < 2; mf++) {
                ldmat4(ah[mf], as + mf * 1280u + a_off + kk * 32u);
                ldmat4(al[mf], ls + mf * 1280u + a_off + kk * 32u);
            }
            ldmat4t(bh, bs + b_off + kk * 4352u);
            ldmat4t(bl, cs + b_off + kk * 4352u);
#pragma unroll
            for (int nf = 0; nf < 2; nf++)
#pragma unroll
                for (int mf = 0; mf < 2; mf++)
                    mma16816(acc[mf][nf], ah[mf], &bh[nf * 2]);
#pragma unroll
            for (int nf = 0; nf < 2; nf++)
#pragma unroll
                for (int mf = 0; mf < 2; mf++)
                    mma16816(acc[mf][nf], ah[mf], &bl[nf * 2]);
#pragma unroll
            for (int nf = 0; nf < 2; nf++)
#pragma unroll
                for (int mf = 0; mf < 2; mf++)
                    mma16816(acc[mf][nf], al[mf], &bh[nf * 2]);
        }
    }

    const int ra = lane >> 2, ka = lane & 3;
#pragma unroll
    for (int mf = 0; mf < 2; mf++)
#pragma unroll
        for (int nf = 0; nf < 2; nf++)
#pragma unroll
            for (int h = 0; h < 2; h++) {
                int row = mf * 16 + ra + h * 8;
                int col = bn + warp * 16 + nf * 8 + ka * 2;
                *(float2*)&fxpart[(size_t)(blockIdx.y * 32 + row) * 1024 + col] =
                    make_float2(acc[mf][nf][h * 2], acc[mf][nf][h * 2 + 1]);
            }
}

// reduce partials (+bias / dummy) -> bf16 hi/lo anchor rows of h
__global__ void fx_reduce(const float* __restrict__ fxpart,
                          const float* __restrict__ dummy,
                          const float* __restrict__ bias,
                          bf16* __restrict__ hhi, bf16* __restrict__ hlo)
{
    int col = blockIdx.x * 128 + threadIdx.x;
    int c = blockIdx.y;
    float v;
    if (c == 0) {
        v = dummy[col];
    } else {
        int m = c - 1;
        float s = bias[col];
#pragma unroll 8
        for (int sl = 0; sl < CSLICES; sl++)
            s += fxpart[(size_t)(sl * 32 + m) * 1024 + col];
        v = s;
    }
    int hrow = (c < 32) ? c * 65 : 2080;
    bf16 h = __float2bfloat16(v);
    hhi[(size_t)hrow * CATD + col] = h;
    hlo[(size_t)hrow * CATD + col] = __float2bfloat16(v - __bfloat162float(h));
}

// ---------------------------------------------------------------------------
// Sparse CAT attention: K/V staged in smem, key-per-lane scores.
// ---------------------------------------------------------------------------
#define KPAD 68
#define ATTN_SMEM ((97 * KPAD * 2 + 8 * 64 + 8 * 100) * 4)

__global__ __launch_bounds__(256)
void attn_kernel(const float* __restrict__ qkv,
                 bf16* __restrict__ yhi, bf16* __restrict__ ylo)
{
    extern __shared__ float dyn[];
    float* sK = dyn;
    float* sV = sK + 97 * KPAD;
    float* sq = sV + 97 * KPAD;
    float* sp = sq + 8 * 64;

    const int cq = blockIdx.x;
    const int head = blockIdx.y;
    const int tid = threadIdx.x;
    const int warp = tid >> 5, lane = tid & 31;
    const int cnt = (cq == 32) ? 1 : 65;
    const int total = cq + cnt;

    for (int idx = tid; idx < total * 16; idx += 256) {
        int kk = idx >> 4, seg = idx & 15;
        int kp = (kk < cq) ? kk * 65 : cq * 65 + (kk - cq);
        const float* base = qkv + (size_t)kp * 3072 + head * 64 + seg * 4;
        float4 kv = *(const float4*)(base + 1024);
        float4 vv = *(const float4*)(base + 2048);
        *(float4*)&sK[kk * KPAD + seg * 4] = kv;
        *(float4*)&sV[kk * KPAD + seg * 4] = vv;
    }
    __syncthreads();

    for (int j = warp; j < cnt; j += 8) {
        const int p = cq * 65 + j;
        const int nk = cq + j + 1;

        float2 q2 = *(const float2*)(qkv + (size_t)p * 3072 + head * 64 + 2 * lane);
        sq[warp * 64 + 2 * lane]     = q2.x;
        sq[warp * 64 + 2 * lane + 1] = q2.y;
        __syncwarp();

        float mx = -1e30f;
        for (int kb2 = 0; kb2 < nk; kb2 += 32) {
            int kk = kb2 + lane;
            float s = -1e30f;
            if (kk < nk) {
                float a = 0.f;
#pragma unroll
                for (int d4 = 0; d4 < 16; d4++) {
                    float4 qv = *(const float4*)&sq[warp * 64 + d4 * 4];
                    float4 kv = *(const float4*)&sK[kk * KPAD + d4 * 4];
                    a += qv.x * kv.x + qv.y * kv.y + qv.z * kv.z + qv.w * kv.w;
                }
                s = a * 0.125f;
                sp[warp * 100 + kk] = s;
            }
            mx = fmaxf(mx, s);
        }
        mx = fmaxf(mx, __shfl_xor_sync(0xffffffffu, mx, 16));
        mx = fmaxf(mx, __shfl_xor_sync(0xffffffffu, mx, 8));
        mx = fmaxf(mx, __shfl_xor_sync(0xffffffffu, mx, 4));
        mx = fmaxf(mx, __shfl_xor_sync(0xffffffffu, mx, 2));
        mx = fmaxf(mx, __shfl_xor_sync(0xffffffffu, mx, 1));
        __syncwarp();

        float sum = 0.f;
        for (int kk = lane; kk < nk; kk += 32) {
            float e = __expf(sp[warp * 100 + kk] - mx);
            sp[warp * 100 + kk] = e;
            sum += e;
        }
        sum += __shfl_xor_sync(0xffffffffu, sum, 16);
        sum += __shfl_xor_sync(0xffffffffu, sum, 8);
        sum += __shfl_xor_sync(0xffffffffu, sum, 4);
        sum += __shfl_xor_sync(0xffffffffu, sum, 2);
        sum += __shfl_xor_sync(0xffffffffu, sum, 1);
        __syncwarp();
        float inv = 1.f / sum;

        float2 acc = make_float2(0.f, 0.f);
        for (int kk = 0; kk < nk; kk++) {
            float pr = sp[warp * 100 + kk];
            float2 v2 = *(const float2*)&sV[kk * KPAD + 2 * lane];
            acc.x += pr * v2.x;
            acc.y += pr * v2.y;
        }
        st_bf16pair(yhi, ylo, (size_t)p * CATD + head * 64 + 2 * lane,
                    acc.x * inv, acc.y * inv);
        __syncwarp();
    }
}

// ---------------------------------------------------------------------------
extern "C" void kernel_launch(void* const* d_in, const int* in_sizes, int n_in,
                              void* d_out, int out_size)
{
    const float* x        = (const float*)d_in[0];
    const float* W_expand = (const float*)d_in[1];
    const float* W_comp   = (const float*)d_in[2];
    const float* b_comp   = (const float*)d_in[3];
    const float* dummy_fx = (const float*)d_in[4];
    const float* W_qkv    = (const float*)d_in[5];
    const float* W_o      = (const float*)d_in[6];
    const float* W_final  = (const float*)d_in[7];
    const float* cosb     = (const float*)d_in[8];
    const float* sinb     = (const float*)d_in[9];
    float* out = (float*)d_out;

    float *fxpart, *qkv;
    bf16 *xhi, *xlo, *hhi, *hlo, *yhi, *ylo, *y2hi, *y2lo;
    bf16 *wexphi, *wexplo, *wqkvhi, *wqkvlo, *wohi, *wolo, *wfinhi, *wfinlo;
    cudaGetSymbolAddress((void**)&fxpart, g_fxpart);
    cudaGetSymbolAddress((void**)&qkv,    g_qkv);
    cudaGetSymbolAddress((void**)&xhi,    g_xhi);
    cudaGetSymbolAddress((void**)&xlo,    g_xlo);
    cudaGetSymbolAddress((void**)&hhi,    g_hhi);
    cudaGetSymbolAddress((void**)&hlo,    g_hlo);
    cudaGetSymbolAddress((void**)&yhi,    g_yhi);
    cudaGetSymbolAddress((void**)&ylo,    g_ylo);
    cudaGetSymbolAddress((void**)&y2hi,   g_y2hi);
    cudaGetSymbolAddress((void**)&y2lo,   g_y2lo);
    cudaGetSymbolAddress((void**)&wexphi, g_wexphi);
    cudaGetSymbolAddress((void**)&wexplo, g_wexplo);
    cudaGetSymbolAddress((void**)&wqkvhi, g_wqkvhi);
    cudaGetSymbolAddress((void**)&wqkvlo, g_wqkvlo);
    cudaGetSymbolAddress((void**)&wohi,   g_wohi);
    cudaGetSymbolAddress((void**)&wolo,   g_wolo);
    cudaGetSymbolAddress((void**)&wfinhi, g_wfinhi);
    cudaGetSymbolAddress((void**)&wfinlo, g_wfinlo);

    cudaFuncSetAttribute((const void*)mma_gemm<0, 1, 64>,  cudaFuncAttributeMaxDynamicSharedMemorySize, DSMEM64);
    cudaFuncSetAttribute((const void*)mma_gemm<0, 3, 128>, cudaFuncAttributeMaxDynamicSharedMemorySize, DSMEM128);
    cudaFuncSetAttribute((const void*)mma_gemm<0, 2, 64>,  cudaFuncAttributeMaxDynamicSharedMemorySize, DSMEM64);
    cudaFuncSetAttribute((const void*)mma_gemm<1, 0, 64>,  cudaFuncAttributeMaxDynamicSharedMemorySize, DSMEM64);
    cudaFuncSetAttribute(attn_kernel, cudaFuncAttributeMaxDynamicSharedMemorySize, ATTN_SMEM);

    // launches 0-2: conversions needed before the first GEMMs
    cvt_kernel<<<2048, 256>>>(x,        xhi,    xlo,    524288);
    cvt_kernel<<<1024, 256>>>(W_expand, wexphi, wexplo, 262144);
    cvt_kernel<<<3072, 256>>>(W_qkv,    wqkvhi, wqkvlo, 786432);

    // launch 3: fx partials (tensor-core split-K, 2-deep prefetch)
    comp_kernel<<<dim3(8, CSLICES), 256>>>(xhi, xlo, W_comp, fxpart);

    // launch 4: reduce partials -> bf16 anchor rows of h
    fx_reduce<<<dim3(8, 33), 128>>>(fxpart, dummy_fx, b_comp, hhi, hlo);

    // launch 5 (profile target): xe = x @ W_expand -> scattered bf16 rows of h
    mma_gemm<0, 1, 64><<<dim3(8, 32), 128, DSMEM64>>>(xhi, xlo, wexphi, wexplo,
                                                      nullptr, hhi, hlo, nullptr, nullptr,
                                                      2048, 1024, 1024);

    // launch 6: qkv = h @ W_qkv (fp32 out, RoPE fused for q/k)
    mma_gemm<0, 3, 128><<<dim3(24, 17), 256, DSMEM128>>>(hhi, hlo, wqkvhi, wqkvlo,
                                                         qkv, nullptr, nullptr, cosb, sinb,
                                                         S_LEN, 3072, 1024);

    // remaining weight conversions
    cvt_kernel<<<1024, 256>>>(W_o,      wohi,   wolo,   262144);
    cvt_kernel<<<1024, 256>>>(W_final,  wfinhi, wfinlo, 262144);

    // sparse CAT attention -> bf16 y
    attn_kernel<<<dim3(33, 16), 256, ATTN_SMEM>>>(qkv, yhi, ylo);

    // y2 = y @ W_o (bf16 out)
    mma_gemm<0, 2, 64><<<dim3(8, 33), 128, DSMEM64>>>(yhi, ylo, wohi, wolo,
                                                      nullptr, y2hi, y2lo, nullptr, nullptr,
                                                      S_LEN, 1024, 1024);

    // out = gather(y2) @ W_final (fp32 out)
    mma_gemm<1, 0, 64><<<dim3(8, 32), 128, DSMEM64>>>(y2hi, y2lo, wfinhi, wfinlo,
                                                      out, nullptr, nullptr, nullptr, nullptr,
                                                      2048, 1024, 1024);
}

// round 11
// speedup vs baseline: 1.1788x; 1.1788x over previous
#include <cuda_runtime.h>
#include <cuda_bf16.h>
#include <math.h>
#include <stdint.h>

// ---------------------------------------------------------------------------
// CAT_Attention (B=1, BLOCK=2048, CHUNK=64, DIM=1024, CAT=1024, NH=16, HD=64)
// S = 2081, W = 65, NC = 32
// Round 11: comp reverted to round-9 version (112us measured); all dense
// GEMMs on BM=64 engine (qkv tail fix: 792 CTAs); merged cvt kernel.
// ---------------------------------------------------------------------------

#define S_LEN   2081
#define CATD    1024
#define NHEAD   16
#define CSLICES 64

typedef __nv_bfloat16 bf16;
typedef __nv_bfloat162 bf162;

// -------------------- scratch (device globals; no allocs) -------------------
__device__ float g_fxpart[CSLICES * 32 * 1024];
__device__ float g_qkv [S_LEN * 3 * CATD];
__device__ bf16  g_xhi[2048 * 1024],  g_xlo[2048 * 1024];
__device__ bf16  g_hhi[S_LEN * 1024], g_hlo[S_LEN * 1024];
__device__ bf16  g_yhi[S_LEN * 1024], g_ylo[S_LEN * 1024];
__device__ bf16  g_y2hi[S_LEN * 1024], g_y2lo[S_LEN * 1024];
__device__ bf16  g_wexphi[1024 * 1024], g_wexplo[1024 * 1024];
__device__ bf16  g_wqkvhi[1024 * 3072], g_wqkvlo[1024 * 3072];
__device__ bf16  g_wohi[1024 * 1024],   g_wolo[1024 * 1024];
__device__ bf16  g_wfinhi[1024 * 1024], g_wfinlo[1024 * 1024];

// -------------------- row maps ---------------------------------------------
__device__ __forceinline__ int amap_final(int r) {
    if (r < 63)    return r + 1;
    if (r == 2047) return 2080;
    int u = r - 63;
    return 65 + u + (u >> 6);
}

// -------------------- helpers ----------------------------------------------
__device__ __forceinline__ uint32_t smem_u32(const void* p) {
    return (uint32_t)__cvta_generic_to_shared(p);
}

__device__ __forceinline__ void cp16(uint32_t dst, const void* src) {
    asm volatile("cp.async.cg.shared.global [%0], [%1], 16;\n" :: "r"(dst), "l"(src));
}

__device__ __forceinline__ void mma16816(float* c, const uint32_t* a, const uint32_t* b) {
    asm volatile(
        "mma.sync.aligned.m16n8k16.row.col.f32.bf16.bf16.f32 "
        "{%0,%1,%2,%3}, {%4,%5,%6,%7}, {%8,%9}, {%0,%1,%2,%3};"
        : "+f"(c[0]), "+f"(c[1]), "+f"(c[2]), "+f"(c[3])
        : "r"(a[0]), "r"(a[1]), "r"(a[2]), "r"(a[3]), "r"(b[0]), "r"(b[1]));
}

__device__ __forceinline__ void ldmat4(uint32_t* r, uint32_t addr) {
    asm volatile(
        "ldmatrix.sync.aligned.m8n8.x4.shared.b16 {%0,%1,%2,%3}, [%4];"
        : "=r"(r[0]), "=r"(r[1]), "=r"(r[2]), "=r"(r[3]) : "r"(addr));
}

__device__ __forceinline__ void ldmat4t(uint32_t* r, uint32_t addr) {
    asm volatile(
        "ldmatrix.sync.aligned.m8n8.x4.trans.shared.b16 {%0,%1,%2,%3}, [%4];"
        : "=r"(r[0]), "=r"(r[1]), "=r"(r[2]), "=r"(r[3]) : "r"(addr));
}

__device__ __forceinline__ void split2(float a, float b, uint32_t& hi, uint32_t& lo) {
    bf16 h0 = __float2bfloat16(a), h1 = __float2bfloat16(b);
    bf16 l0 = __float2bfloat16(a - __bfloat162float(h0));
    bf16 l1 = __float2bfloat16(b - __bfloat162float(h1));
    bf162 hh = __halves2bfloat162(h0, h1), ll = __halves2bfloat162(l0, l1);
    hi = *(uint32_t*)&hh; lo = *(uint32_t*)&ll;
}

__device__ __forceinline__ void st_bf16pair(bf16* hi, bf16* lo, size_t idx,
                                            float v0, float v1) {
    uint32_t h, l;
    split2(v0, v1, h, l);
    *(uint32_t*)(hi + idx) = h;
    *(uint32_t*)(lo + idx) = l;
}

// ---------------------------------------------------------------------------
// merged convert: all 5 tensors in ONE launch; 2 float4 per thread.
// block ranges (each block = 512 float4): x 1024 | wexp 512 | wqkv 1536 |
// wo 512 | wfin 512  -> 4096 blocks total.
// ---------------------------------------------------------------------------
__global__ __launch_bounds__(256)
void cvt_all(const float* __restrict__ s0, bf16* __restrict__ h0, bf16* __restrict__ l0,
             const float* __restrict__ s1, bf16* __restrict__ h1, bf16* __restrict__ l1,
             const float* __restrict__ s2, bf16* __restrict__ h2, bf16* __restrict__ l2,
             const float* __restrict__ s3, bf16* __restrict__ h3, bf16* __restrict__ l3,
             const float* __restrict__ s4, bf16* __restrict__ h4, bf16* __restrict__ l4)
{
    int b = blockIdx.x;
    const float* src; bf16 *hi, *lo; int base;
    if (b < 1024)      { src = s0; hi = h0; lo = l0; base = b; }
    else if (b < 1536) { src = s1; hi = h1; lo = l1; base = b - 1024; }
    else if (b < 3072) { src = s2; hi = h2; lo = l2; base = b - 1536; }
    else if (b < 3584) { src = s3; hi = h3; lo = l3; base = b - 3072; }
    else               { src = s4; hi = h4; lo = l4; base = b - 3584; }

    int i0 = base * 512 + threadIdx.x;
#pragma unroll
    for (int p = 0; p < 2; p++) {
        int i = i0 + p * 256;
        float4 v = ((const float4*)src)[i];
        uint2 uh, ul;
        split2(v.x, v.y, uh.x, ul.x);
        split2(v.z, v.w, uh.y, ul.y);
        *(uint2*)(hi + 4 * (size_t)i) = uh;
        *(uint2*)(lo + 4 * (size_t)i) = ul;
    }
}

// ---------------------------------------------------------------------------
// GEMM engine v3.2 (BM=64): 128 threads, 4 warps, warp tile 32x64,
// XOR-swizzled smem, 3-stage cp.async, 1 sync/iter, term-major mma.
// AMODE: 0 identity, 1 gather amap_final.
// CMODE: 0 fp32 C, 1 bf16 scatter->h, 2 bf16 identity, 3 fp32 + fused RoPE.
// ---------------------------------------------------------------------------
template<int AMODE, int CMODE, int BM>
__global__ __launch_bounds__(BM * 2, BM == 128 ? 2 : 3)
void mma_gemm(const bf16* __restrict__ Agh, const bf16* __restrict__ Agl,
              const bf16* __restrict__ Bgh, const bf16* __restrict__ Bgl,
              float* __restrict__ C, bf16* __restrict__ Chi, bf16* __restrict__ Clo,
              const float* __restrict__ cosb, const float* __restrict__ sinb,
              int M, int N, int K)
{
    constexpr int NT = BM * 2;
    constexpr uint32_t ASZ = (uint32_t)BM * 64u;
    constexpr uint32_t STG = 2u * ASZ + 16384u;
    constexpr int BPASS = 512 / NT;
    constexpr int BROWS = NT / 16;

    extern __shared__ char dsm[];
    const uint32_t sb = smem_u32(dsm);
    const int tid = threadIdx.x, lane = tid & 31, wid = tid >> 5;
    const int warp_m = wid & (BM / 32 - 1), warp_n = wid / (BM / 32);
    const int bm = blockIdx.y * BM, bn = blockIdx.x * 128;

    size_t aoff[2];
#pragma unroll
    for (int i = 0; i < 2; i++) {
        int gr = bm + (tid >> 2) + i * (BM / 2);
        int r = (gr < M) ? gr : 0;
        if (AMODE == 1) r = amap_final(r);
        aoff[i] = (size_t)r * K + (tid & 3) * 8;
    }
    const int arow0 = tid >> 2;
    const uint32_t aswz = (uint32_t)(((tid & 3) ^ ((arow0 >> 1) & 3)) << 4);
    uint32_t a_dst[2];
#pragma unroll
    for (int i = 0; i < 2; i++) a_dst[i] = (uint32_t)((arow0 + i * (BM / 2)) * 64) + aswz;

    const int krow0 = tid >> 4;
    const size_t b_col = (size_t)bn + (tid & 15) * 8;
    const uint32_t bswz = (uint32_t)((((tid & 15) ^ (krow0 & 7))) << 4);
    uint32_t b_dst[BPASS];
#pragma unroll
    for (int i = 0; i < BPASS; i++) b_dst[i] = (uint32_t)((krow0 + i * BROWS) * 256) + bswz;

    const int quad = lane >> 3, lrow = lane & 7;
    const int c2 = quad >> 1;
    const int rowLocal = (quad & 1) * 8 + lrow;
    const uint32_t aRowByte = (uint32_t)((warp_m * 32 + rowLocal) * 64);
    const int swA = (rowLocal >> 1) & 3;
    const uint32_t bRowByte = (uint32_t)(rowLocal * 256);

    float acc[16][4];
#pragma unroll
    for (int i = 0; i < 16; i++)
#pragma unroll
        for (int j = 0; j < 4; j++) acc[i][j] = 0.f;

    const int NIT = K >> 5;

    auto issue = [&](int it) {
        const int k0 = it << 5;
        const uint32_t st = sb + (uint32_t)(it % 3) * STG;
#pragma unroll
        for (int i = 0; i < 2; i++) {
            cp16(st + a_dst[i],       Agh + aoff[i] + k0);
            cp16(st + ASZ + a_dst[i], Agl + aoff[i] + k0);
        }
#pragma unroll
        for (int i = 0; i < BPASS; i++) {
            size_t src = (size_t)(k0 + krow0 + i * BROWS) * N + b_col;
            cp16(st + 2u * ASZ + b_dst[i],          Bgh + src);
            cp16(st + 2u * ASZ + 8192u + b_dst[i],  Bgl + src);
        }
        asm volatile("cp.async.commit_group;\n" ::: "memory");
    };

    issue(0);
    issue(1);
    for (int it = 0; it < NIT; it++) {
        if (it + 1 < NIT)
            asm volatile("cp.async.wait_group 1;\n" ::: "memory");
        else
            asm volatile("cp.async.wait_group 0;\n" ::: "memory");
        __syncthreads();
        if (it + 2 < NIT) issue(it + 2);

        const uint32_t st = sb + (uint32_t)(it % 3) * STG;
#pragma unroll
        for (int kk = 0; kk < 2; kk++) {
            uint32_t ah[2][4], al[2][4];
#pragma unroll
            for (int mf = 0; mf < 2; mf++) {
                uint32_t achunk = (uint32_t)((((kk * 2 + c2) ^ swA)) << 4);
                uint32_t aaddr = st + aRowByte + (uint32_t)(mf * 1024) + achunk;
                ldmat4(ah[mf], aaddr);
                ldmat4(al[mf], aaddr + ASZ);
            }
            const uint32_t bk = st + 2u * ASZ + (uint32_t)(kk * 16 * 256) + bRowByte;
#pragma unroll
            for (int j = 0; j < 4; j++) {
                uint32_t bh[4], bl[4];
                uint32_t bchunk = (uint32_t)(((warp_n * 8 + c2 + j * 2) ^ lrow) << 4);
                ldmat4t(bh, bk + bchunk);
                ldmat4t(bl, bk + bchunk + 8192u);
#pragma unroll
                for (int h = 0; h < 2; h++)
#pragma unroll
                    for (int mf = 0; mf < 2; mf++)
                        mma16816(acc[mf * 8 + j * 2 + h], ah[mf], &bh[h * 2]);
#pragma unroll
                for (int h = 0; h < 2; h++)
#pragma unroll
                    for (int mf = 0; mf < 2; mf++)
                        mma16816(acc[mf * 8 + j * 2 + h], ah[mf], &bl[h * 2]);
#pragma unroll
                for (int h = 0; h < 2; h++)
#pragma unroll
                    for (int mf = 0; mf < 2; mf++)
                        mma16816(acc[mf * 8 + j * 2 + h], al[mf], &bh[h * 2]);
            }
        }
    }

    // ---- epilogue ----
    const int ra = lane >> 2, ka = lane & 3;
    const int colBase = bn + warp_n * 64;

    if (CMODE == 3 && colBase < 2048) {
#pragma unroll
        for (int mf = 0; mf < 2; mf++)
#pragma unroll
            for (int hh = 0; hh < 2; hh++) {
                int gr = bm + warp_m * 32 + mf * 16 + ra + hh * 8;
                if (gr >= M) continue;
                const float* cb = cosb + (size_t)gr * 64;
                const float* sn = sinb + (size_t)gr * 64;
#pragma unroll
                for (int nf = 0; nf < 4; nf++) {
                    int d = nf * 8 + ka * 2;
                    float a0 = acc[mf * 8 + nf][hh * 2];
                    float a1 = acc[mf * 8 + nf][hh * 2 + 1];
                    float b0 = acc[mf * 8 + nf + 4][hh * 2];
                    float b1 = acc[mf * 8 + nf + 4][hh * 2 + 1];
                    float o0 = a0 * cb[d]     - b0 * sn[d];
                    float o1 = a1 * cb[d + 1] - b1 * sn[d + 1];
                    float p0 = b0 * cb[d + 32] + a0 * sn[d + 32];
                    float p1 = b1 * cb[d + 33] + a1 * sn[d + 33];
                    *(float2*)&C[(size_t)gr * N + colBase + d]      = make_float2(o0, o1);
                    *(float2*)&C[(size_t)gr * N + colBase + d + 32] = make_float2(p0, p1);
                }
            }
        return;
    }

#pragma unroll
    for (int mf = 0; mf < 2; mf++)
#pragma unroll
        for (int nf = 0; nf < 8; nf++) {
            const float* c = acc[mf * 8 + nf];
            int col = colBase + nf * 8 + ka * 2;
#pragma unroll
            for (int h = 0; h < 2; h++) {
                int gr = bm + warp_m * 32 + mf * 16 + ra + h * 8;
                if (gr >= M) continue;
                float v0 = c[h * 2], v1 = c[h * 2 + 1];
                if (CMODE == 0 || CMODE == 3) {
                    *(float2*)&C[(size_t)gr * N + col] = make_float2(v0, v1);
                } else {
                    int cr = (CMODE == 1) ? ((gr >> 6) * 65 + 1 + (gr & 63)) : gr;
                    st_bf16pair(Chi, Clo, (size_t)cr * N + col, v0, v1);
                }
            }
        }
}

#define DSMEM64  73728

// ---------------------------------------------------------------------------
// comp GEMM (round-9 version, measured 112us): fx = x @ W_comp, split-K.
// Single-stage smem, register prefetch 1-deep, 2 syncs/iter, term-major.
// ---------------------------------------------------------------------------
__global__ __launch_bounds__(256)
void comp_kernel(const bf16* __restrict__ xhi, const bf16* __restrict__ xlo,
                 const float* __restrict__ Wc, float* __restrict__ fxpart)
{
    __shared__ bf16 Ahi[32][40], Alo[32][40];
    __shared__ bf16 Bhi[32][136], Blo[32][136];

    const int tid = threadIdx.x, lane = tid & 31, warp = tid >> 5;
    const int bn = blockIdx.x * 128;
    const int kb = blockIdx.y * 1024;

    const int wr = tid >> 3, wc = (tid & 7) * 16;
    const int xr = tid >> 3, xc = (tid & 7) * 4;

    float4 wreg[4];
    uint2 xh, xl;
    auto loadNext = [&](int k0) {
        const float* wp = Wc + (size_t)(kb + k0 + wr) * 1024 + bn + wc;
#pragma unroll
        for (int i = 0; i < 4; i++) wreg[i] = *(const float4*)(wp + i * 4);
        size_t xoff = (size_t)xr * 65536 + kb + k0 + xc;
        xh = *(const uint2*)(xhi + xoff);
        xl = *(const uint2*)(xlo + xoff);
    };

    float acc[2][2][4];
#pragma unroll
    for (int i = 0; i < 2; i++)
#pragma unroll
        for (int j = 0; j < 2; j++)
#pragma unroll
            for (int q = 0; q < 4; q++) acc[i][j][q] = 0.f;

    const uint32_t ah_base = smem_u32(&Ahi[0][0]);
    const uint32_t al_base = smem_u32(&Alo[0][0]);
    const uint32_t bh_base = smem_u32(&Bhi[0][0]);
    const uint32_t bl_base = smem_u32(&Blo[0][0]);
    const int quad = lane >> 3, lrow = lane & 7;
    const uint32_t a_off = (uint32_t)(((quad & 1) * 8 + lrow) * 80 + (quad >> 1) * 16);
    const uint32_t b_off = (uint32_t)(((quad & 1) * 8 + lrow) * 272 + (warp * 16 + (quad >> 1) * 8) * 2);

    loadNext(0);
    for (int k0 = 0; k0 < 1024; k0 += 32) {
        __syncthreads();
#pragma unroll
        for (int i = 0; i < 4; i++) {
            float4 v = wreg[i];
            uint2 uh, ul;
            split2(v.x, v.y, uh.x, ul.x);
            split2(v.z, v.w, uh.y, ul.y);
            *(uint2*)&Bhi[wr][wc + i * 4] = uh;
            *(uint2*)&Blo[wr][wc + i * 4] = ul;
        }
        *(uint2*)&Ahi[xr][xc] = xh;
        *(uint2*)&Alo[xr][xc] = xl;
        __syncthreads();
        if (k0 + 32 < 1024) loadNext(k0 + 32);

#pragma unroll
        for (int kk = 0; kk < 2; kk++) {
            uint32_t ah[2][4], al[2][4], bh[4], bl[4];
#pragma unroll
            for (int mf = 0; mf < 2; mf++) {
                ldmat4(ah[mf], ah_base + mf * 1280u + a_off + kk * 32u);
                ldmat4(al[mf], al_base + mf * 1280u + a_off + kk * 32u);
            }
            ldmat4t(bh, bh_base + b_off + kk * 4352u);
            ldmat4t(bl, bl_base + b_off + kk * 4352u);
#pragma unroll
            for (int nf = 0; nf < 2; nf++)
#pragma unroll
                for (int mf = 0; mf < 2; mf++)
                    mma16816(acc[mf][nf], ah[mf], &bh[nf * 2]);
#pragma unroll
            for (int nf = 0; nf < 2; nf++)
#pragma unroll
                for (int mf = 0; mf < 2; mf++)
                    mma16816(acc[mf][nf], ah[mf], &bl[nf * 2]);
#pragma unroll
            for (int nf = 0; nf < 2; nf++)
#pragma unroll
                for (int mf = 0; mf < 2; mf++)
                    mma16816(acc[mf][nf], al[mf], &bh[nf * 2]);
        }
    }

    const int ra = lane >> 2, ka = lane & 3;
#pragma unroll
    for (int mf = 0; mf < 2; mf++)
#pragma unroll
        for (int nf = 0; nf < 2; nf++)
#pragma unroll
            for (int h = 0; h < 2; h++) {
                int row = mf * 16 + ra + h * 8;
                int col = bn + warp * 16 + nf * 8 + ka * 2;
                *(float2*)&fxpart[(size_t)(blockIdx.y * 32 + row) * 1024 + col] =
                    make_float2(acc[mf][nf][h * 2], acc[mf][nf][h * 2 + 1]);
            }
}

// reduce partials (+bias / dummy) -> bf16 hi/lo anchor rows of h
__global__ void fx_reduce(const float* __restrict__ fxpart,
                          const float* __restrict__ dummy,
                          const float* __restrict__ bias,
                          bf16* __restrict__ hhi, bf16* __restrict__ hlo)
{
    int col = blockIdx.x * 128 + threadIdx.x;
    int c = blockIdx.y;
    float v;
    if (c == 0) {
        v = dummy[col];
    } else {
        int m = c - 1;
        float s = bias[col];
#pragma unroll 8
        for (int sl = 0; sl < CSLICES; sl++)
            s += fxpart[(size_t)(sl * 32 + m) * 1024 + col];
        v = s;
    }
    int hrow = (c < 32) ? c * 65 : 2080;
    bf16 h = __float2bfloat16(v);
    hhi[(size_t)hrow * CATD + col] = h;
    hlo[(size_t)hrow * CATD + col] = __float2bfloat16(v - __bfloat162float(h));
}

// ---------------------------------------------------------------------------
// Sparse CAT attention: K/V staged in smem, key-per-lane scores.
// ---------------------------------------------------------------------------
#define KPAD 68
#define ATTN_SMEM ((97 * KPAD * 2 + 8 * 64 + 8 * 100) * 4)

__global__ __launch_bounds__(256)
void attn_kernel(const float* __restrict__ qkv,
                 bf16* __restrict__ yhi, bf16* __restrict__ ylo)
{
    extern __shared__ float dyn[];
    float* sK = dyn;
    float* sV = sK + 97 * KPAD;
    float* sq = sV + 97 * KPAD;
    float* sp = sq + 8 * 64;

    const int cq = blockIdx.x;
    const int head = blockIdx.y;
    const int tid = threadIdx.x;
    const int warp = tid >> 5, lane = tid & 31;
    const int cnt = (cq == 32) ? 1 : 65;
    const int total = cq + cnt;

    for (int idx = tid; idx < total * 16; idx += 256) {
        int kk = idx >> 4, seg = idx & 15;
        int kp = (kk < cq) ? kk * 65 : cq * 65 + (kk - cq);
        const float* base = qkv + (size_t)kp * 3072 + head * 64 + seg * 4;
        float4 kv = *(const float4*)(base + 1024);
        float4 vv = *(const float4*)(base + 2048);
        *(float4*)&sK[kk * KPAD + seg * 4] = kv;
        *(float4*)&sV[kk * KPAD + seg * 4] = vv;
    }
    __syncthreads();

    for (int j = warp; j < cnt; j += 8) {
        const int p = cq * 65 + j;
        const int nk = cq + j + 1;

        float2 q2 = *(const float2*)(qkv + (size_t)p * 3072 + head * 64 + 2 * lane);
        sq[warp * 64 + 2 * lane]     = q2.x;
        sq[warp * 64 + 2 * lane + 1] = q2.y;
        __syncwarp();

        float mx = -1e30f;
        for (int kb2 = 0; kb2 < nk; kb2 += 32) {
            int kk = kb2 + lane;
            float s = -1e30f;
            if (kk < nk) {
                float a = 0.f;
#pragma unroll
                for (int d4 = 0; d4 < 16; d4++) {
                    float4 qv = *(const float4*)&sq[warp * 64 + d4 * 4];
                    float4 kv = *(const float4*)&sK[kk * KPAD + d4 * 4];
                    a += qv.x * kv.x + qv.y * kv.y + qv.z * kv.z + qv.w * kv.w;
                }
                s = a * 0.125f;
                sp[warp * 100 + kk] = s;
            }
            mx = fmaxf(mx, s);
        }
        mx = fmaxf(mx, __shfl_xor_sync(0xffffffffu, mx, 16));
        mx = fmaxf(mx, __shfl_xor_sync(0xffffffffu, mx, 8));
        mx = fmaxf(mx, __shfl_xor_sync(0xffffffffu, mx, 4));
        mx = fmaxf(mx, __shfl_xor_sync(0xffffffffu, mx, 2));
        mx = fmaxf(mx, __shfl_xor_sync(0xffffffffu, mx, 1));
        __syncwarp();

        float sum = 0.f;
        for (int kk = lane; kk < nk; kk += 32) {
            float e = __expf(sp[warp * 100 + kk] - mx);
            sp[warp * 100 + kk] = e;
            sum += e;
        }
        sum += __shfl_xor_sync(0xffffffffu, sum, 16);
        sum += __shfl_xor_sync(0xffffffffu, sum, 8);
        sum += __shfl_xor_sync(0xffffffffu, sum, 4);
        sum += __shfl_xor_sync(0xffffffffu, sum, 2);
        sum += __shfl_xor_sync(0xffffffffu, sum, 1);
        __syncwarp();
        float inv = 1.f / sum;

        float2 acc = make_float2(0.f, 0.f);
        for (int kk = 0; kk < nk; kk++) {
            float pr = sp[warp * 100 + kk];
            float2 v2 = *(const float2*)&sV[kk * KPAD + 2 * lane];
            acc.x += pr * v2.x;
            acc.y += pr * v2.y;
        }
        st_bf16pair(yhi, ylo, (size_t)p * CATD + head * 64 + 2 * lane,
                    acc.x * inv, acc.y * inv);
        __syncwarp();
    }
}

// ---------------------------------------------------------------------------
extern "C" void kernel_launch(void* const* d_in, const int* in_sizes, int n_in,
                              void* d_out, int out_size)
{
    const float* x        = (const float*)d_in[0];
    const float* W_expand = (const float*)d_in[1];
    const float* W_comp   = (const float*)d_in[2];
    const float* b_comp   = (const float*)d_in[3];
    const float* dummy_fx = (const float*)d_in[4];
    const float* W_qkv    = (const float*)d_in[5];
    const float* W_o      = (const float*)d_in[6];
    const float* W_final  = (const float*)d_in[7];
    const float* cosb     = (const float*)d_in[8];
    const float* sinb     = (const float*)d_in[9];
    float* out = (float*)d_out;

    float *fxpart, *qkv;
    bf16 *xhi, *xlo, *hhi, *hlo, *yhi, *ylo, *y2hi, *y2lo;
    bf16 *wexphi, *wexplo, *wqkvhi, *wqkvlo, *wohi, *wolo, *wfinhi, *wfinlo;
    cudaGetSymbolAddress((void**)&fxpart, g_fxpart);
    cudaGetSymbolAddress((void**)&qkv,    g_qkv);
    cudaGetSymbolAddress((void**)&xhi,    g_xhi);
    cudaGetSymbolAddress((void**)&xlo,    g_xlo);
    cudaGetSymbolAddress((void**)&hhi,    g_hhi);
    cudaGetSymbolAddress((void**)&hlo,    g_hlo);
    cudaGetSymbolAddress((void**)&yhi,    g_yhi);
    cudaGetSymbolAddress((void**)&ylo,    g_ylo);
    cudaGetSymbolAddress((void**)&y2hi,   g_y2hi);
    cudaGetSymbolAddress((void**)&y2lo,   g_y2lo);
    cudaGetSymbolAddress((void**)&wexphi, g_wexphi);
    cudaGetSymbolAddress((void**)&wexplo, g_wexplo);
    cudaGetSymbolAddress((void**)&wqkvhi, g_wqkvhi);
    cudaGetSymbolAddress((void**)&wqkvlo, g_wqkvlo);
    cudaGetSymbolAddress((void**)&wohi,   g_wohi);
    cudaGetSymbolAddress((void**)&wolo,   g_wolo);
    cudaGetSymbolAddress((void**)&wfinhi, g_wfinhi);
    cudaGetSymbolAddress((void**)&wfinlo, g_wfinlo);

    cudaFuncSetAttribute((const void*)mma_gemm<0, 1, 64>, cudaFuncAttributeMaxDynamicSharedMemorySize, DSMEM64);
    cudaFuncSetAttribute((const void*)mma_gemm<0, 3, 64>, cudaFuncAttributeMaxDynamicSharedMemorySize, DSMEM64);
    cudaFuncSetAttribute((const void*)mma_gemm<0, 2, 64>, cudaFuncAttributeMaxDynamicSharedMemorySize, DSMEM64);
    cudaFuncSetAttribute((const void*)mma_gemm<1, 0, 64>, cudaFuncAttributeMaxDynamicSharedMemorySize, DSMEM64);
    cudaFuncSetAttribute(attn_kernel, cudaFuncAttributeMaxDynamicSharedMemorySize, ATTN_SMEM);

    // launch 0: all fp32 -> bf16 hi/lo conversions in one kernel
    cvt_all<<<4096, 256>>>(x,        xhi,    xlo,
                           W_expand, wexphi, wexplo,
                           W_qkv,    wqkvhi, wqkvlo,
                           W_o,      wohi,   wolo,
                           W_final,  wfinhi, wfinlo);

    // launch 1: fx partials (tensor-core split-K)
    comp_kernel<<<dim3(8, CSLICES), 256>>>(xhi, xlo, W_comp, fxpart);

    // launch 2: reduce partials -> bf16 anchor rows of h
    fx_reduce<<<dim3(8, 33), 128>>>(fxpart, dummy_fx, b_comp, hhi, hlo);

    // launch 3: xe = x @ W_expand -> scattered bf16 rows of h
    mma_gemm<0, 1, 64><<<dim3(8, 32), 128, DSMEM64>>>(xhi, xlo, wexphi, wexplo,
                                                      nullptr, hhi, hlo, nullptr, nullptr,
                                                      2048, 1024, 1024);

    // launch 4: qkv = h @ W_qkv (fp32 out, RoPE fused for q/k) — 792 CTAs
    mma_gemm<0, 3, 64><<<dim3(24, 33), 128, DSMEM64>>>(hhi, hlo, wqkvhi, wqkvlo,
                                                       qkv, nullptr, nullptr, cosb, sinb,
                                                       S_LEN, 3072, 1024);

    // launch 5 (profile target): sparse CAT attention -> bf16 y
    attn_kernel<<<dim3(33, 16), 256, ATTN_SMEM>>>(qkv, yhi, ylo);

    // y2 = y @ W_o (bf16 out)
    mma_gemm<0, 2, 64><<<dim3(8, 33), 128, DSMEM64>>>(yhi, ylo, wohi, wolo,
                                                      nullptr, y2hi, y2lo, nullptr, nullptr,
                                                      S_LEN, 1024, 1024);

    // out = gather(y2) @ W_final (fp32 out)
    mma_gemm<1, 0, 64><<<dim3(8, 32), 128, DSMEM64>>>(y2hi, y2lo, wfinhi, wfinlo,
                                                      out, nullptr, nullptr, nullptr, nullptr,
                                                      2048, 1024, 1024);
}

// round 12
// speedup vs baseline: 1.2420x; 1.0537x over previous
#include <cuda_runtime.h>
#include <cuda_bf16.h>
#include <math.h>
#include <stdint.h>

// ---------------------------------------------------------------------------
// CAT_Attention (B=1, BLOCK=2048, CHUNK=64, DIM=1024, CAT=1024, NH=16, HD=64)
// S = 2081, W = 65, NC = 32
// Round 12: comp v5 — W_comp streamed as fp32 via 3-stage cp.async ring,
// converted fp32->bf16 in smem; x cp.async'd straight into fragment layout.
// Dense GEMMs / attention / cvt identical to round 11 (442us best).
// ---------------------------------------------------------------------------

#define S_LEN   2081
#define CATD    1024
#define NHEAD   16
#define CSLICES 64

typedef __nv_bfloat16 bf16;
typedef __nv_bfloat162 bf162;

// -------------------- scratch (device globals; no allocs) -------------------
__device__ float g_fxpart[CSLICES * 32 * 1024];
__device__ float g_qkv [S_LEN * 3 * CATD];
__device__ bf16  g_xhi[2048 * 1024],  g_xlo[2048 * 1024];
__device__ bf16  g_hhi[S_LEN * 1024], g_hlo[S_LEN * 1024];
__device__ bf16  g_yhi[S_LEN * 1024], g_ylo[S_LEN * 1024];
__device__ bf16  g_y2hi[S_LEN * 1024], g_y2lo[S_LEN * 1024];
__device__ bf16  g_wexphi[1024 * 1024], g_wexplo[1024 * 1024];
__device__ bf16  g_wqkvhi[1024 * 3072], g_wqkvlo[1024 * 3072];
__device__ bf16  g_wohi[1024 * 1024],   g_wolo[1024 * 1024];
__device__ bf16  g_wfinhi[1024 * 1024], g_wfinlo[1024 * 1024];

// -------------------- row maps ---------------------------------------------
__device__ __forceinline__ int amap_final(int r) {
    if (r < 63)    return r + 1;
    if (r == 2047) return 2080;
    int u = r - 63;
    return 65 + u + (u >> 6);
}

// -------------------- helpers ----------------------------------------------
__device__ __forceinline__ uint32_t smem_u32(const void* p) {
    return (uint32_t)__cvta_generic_to_shared(p);
}

__device__ __forceinline__ void cp16(uint32_t dst, const void* src) {
    asm volatile("cp.async.cg.shared.global [%0], [%1], 16;\n" :: "r"(dst), "l"(src));
}

__device__ __forceinline__ void mma16816(float* c, const uint32_t* a, const uint32_t* b) {
    asm volatile(
        "mma.sync.aligned.m16n8k16.row.col.f32.bf16.bf16.f32 "
        "{%0,%1,%2,%3}, {%4,%5,%6,%7}, {%8,%9}, {%0,%1,%2,%3};"
        : "+f"(c[0]), "+f"(c[1]), "+f"(c[2]), "+f"(c[3])
        : "r"(a[0]), "r"(a[1]), "r"(a[2]), "r"(a[3]), "r"(b[0]), "r"(b[1]));
}

__device__ __forceinline__ void ldmat4(uint32_t* r, uint32_t addr) {
    asm volatile(
        "ldmatrix.sync.aligned.m8n8.x4.shared.b16 {%0,%1,%2,%3}, [%4];"
        : "=r"(r[0]), "=r"(r[1]), "=r"(r[2]), "=r"(r[3]) : "r"(addr));
}

__device__ __forceinline__ void ldmat4t(uint32_t* r, uint32_t addr) {
    asm volatile(
        "ldmatrix.sync.aligned.m8n8.x4.trans.shared.b16 {%0,%1,%2,%3}, [%4];"
        : "=r"(r[0]), "=r"(r[1]), "=r"(r[2]), "=r"(r[3]) : "r"(addr));
}

__device__ __forceinline__ void split2(float a, float b, uint32_t& hi, uint32_t& lo) {
    bf16 h0 = __float2bfloat16(a), h1 = __float2bfloat16(b);
    bf16 l0 = __float2bfloat16(a - __bfloat162float(h0));
    bf16 l1 = __float2bfloat16(b - __bfloat162float(h1));
    bf162 hh = __halves2bfloat162(h0, h1), ll = __halves2bfloat162(l0, l1);
    hi = *(uint32_t*)&hh; lo = *(uint32_t*)&ll;
}

__device__ __forceinline__ void st_bf16pair(bf16* hi, bf16* lo, size_t idx,
                                            float v0, float v1) {
    uint32_t h, l;
    split2(v0, v1, h, l);
    *(uint32_t*)(hi + idx) = h;
    *(uint32_t*)(lo + idx) = l;
}

// ---------------------------------------------------------------------------
// merged convert: all 5 tensors in ONE launch; 2 float4 per thread.
// ---------------------------------------------------------------------------
__global__ __launch_bounds__(256)
void cvt_all(const float* __restrict__ s0, bf16* __restrict__ h0, bf16* __restrict__ l0,
             const float* __restrict__ s1, bf16* __restrict__ h1, bf16* __restrict__ l1,
             const float* __restrict__ s2, bf16* __restrict__ h2, bf16* __restrict__ l2,
             const float* __restrict__ s3, bf16* __restrict__ h3, bf16* __restrict__ l3,
             const float* __restrict__ s4, bf16* __restrict__ h4, bf16* __restrict__ l4)
{
    int b = blockIdx.x;
    const float* src; bf16 *hi, *lo; int base;
    if (b < 1024)      { src = s0; hi = h0; lo = l0; base = b; }
    else if (b < 1536) { src = s1; hi = h1; lo = l1; base = b - 1024; }
    else if (b < 3072) { src = s2; hi = h2; lo = l2; base = b - 1536; }
    else if (b < 3584) { src = s3; hi = h3; lo = l3; base = b - 3072; }
    else               { src = s4; hi = h4; lo = l4; base = b - 3584; }

    int i0 = base * 512 + threadIdx.x;
#pragma unroll
    for (int p = 0; p < 2; p++) {
        int i = i0 + p * 256;
        float4 v = ((const float4*)src)[i];
        uint2 uh, ul;
        split2(v.x, v.y, uh.x, ul.x);
        split2(v.z, v.w, uh.y, ul.y);
        *(uint2*)(hi + 4 * (size_t)i) = uh;
        *(uint2*)(lo + 4 * (size_t)i) = ul;
    }
}

// ---------------------------------------------------------------------------
// GEMM engine v3.2 (BM=64): unchanged from round 11.
// ---------------------------------------------------------------------------
template<int AMODE, int CMODE, int BM>
__global__ __launch_bounds__(BM * 2, BM == 128 ? 2 : 3)
void mma_gemm(const bf16* __restrict__ Agh, const bf16* __restrict__ Agl,
              const bf16* __restrict__ Bgh, const bf16* __restrict__ Bgl,
              float* __restrict__ C, bf16* __restrict__ Chi, bf16* __restrict__ Clo,
              const float* __restrict__ cosb, const float* __restrict__ sinb,
              int M, int N, int K)
{
    constexpr int NT = BM * 2;
    constexpr uint32_t ASZ = (uint32_t)BM * 64u;
    constexpr uint32_t STG = 2u * ASZ + 16384u;
    constexpr int BPASS = 512 / NT;
    constexpr int BROWS = NT / 16;

    extern __shared__ char dsm[];
    const uint32_t sb = smem_u32(dsm);
    const int tid = threadIdx.x, lane = tid & 31, wid = tid >> 5;
    const int warp_m = wid & (BM / 32 - 1), warp_n = wid / (BM / 32);
    const int bm = blockIdx.y * BM, bn = blockIdx.x * 128;

    size_t aoff[2];
#pragma unroll
    for (int i = 0; i < 2; i++) {
        int gr = bm + (tid >> 2) + i * (BM / 2);
        int r = (gr < M) ? gr : 0;
        if (AMODE == 1) r = amap_final(r);
        aoff[i] = (size_t)r * K + (tid & 3) * 8;
    }
    const int arow0 = tid >> 2;
    const uint32_t aswz = (uint32_t)(((tid & 3) ^ ((arow0 >> 1) & 3)) << 4);
    uint32_t a_dst[2];
#pragma unroll
    for (int i = 0; i < 2; i++) a_dst[i] = (uint32_t)((arow0 + i * (BM / 2)) * 64) + aswz;

    const int krow0 = tid >> 4;
    const size_t b_col = (size_t)bn + (tid & 15) * 8;
    const uint32_t bswz = (uint32_t)((((tid & 15) ^ (krow0 & 7))) << 4);
    uint32_t b_dst[BPASS];
#pragma unroll
    for (int i = 0; i < BPASS; i++) b_dst[i] = (uint32_t)((krow0 + i * BROWS) * 256) + bswz;

    const int quad = lane >> 3, lrow = lane & 7;
    const int c2 = quad >> 1;
    const int rowLocal = (quad & 1) * 8 + lrow;
    const uint32_t aRowByte = (uint32_t)((warp_m * 32 + rowLocal) * 64);
    const int swA = (rowLocal >> 1) & 3;
    const uint32_t bRowByte = (uint32_t)(rowLocal * 256);

    float acc[16][4];
#pragma unroll
    for (int i = 0; i < 16; i++)
#pragma unroll
        for (int j = 0; j < 4; j++) acc[i][j] = 0.f;

    const int NIT = K >> 5;

    auto issue = [&](int it) {
        const int k0 = it << 5;
        const uint32_t st = sb + (uint32_t)(it % 3) * STG;
#pragma unroll
        for (int i = 0; i < 2; i++) {
            cp16(st + a_dst[i],       Agh + aoff[i] + k0);
            cp16(st + ASZ + a_dst[i], Agl + aoff[i] + k0);
        }
#pragma unroll
        for (int i = 0; i < BPASS; i++) {
            size_t src = (size_t)(k0 + krow0 + i * BROWS) * N + b_col;
            cp16(st + 2u * ASZ + b_dst[i],          Bgh + src);
            cp16(st + 2u * ASZ + 8192u + b_dst[i],  Bgl + src);
        }
        asm volatile("cp.async.commit_group;\n" ::: "memory");
    };

    issue(0);
    issue(1);
    for (int it = 0; it < NIT; it++) {
        if (it + 1 < NIT)
            asm volatile("cp.async.wait_group 1;\n" ::: "memory");
        else
            asm volatile("cp.async.wait_group 0;\n" ::: "memory");
        __syncthreads();
        if (it + 2 < NIT) issue(it + 2);

        const uint32_t st = sb + (uint32_t)(it % 3) * STG;
#pragma unroll
        for (int kk = 0; kk < 2; kk++) {
            uint32_t ah[2][4], al[2][4];
#pragma unroll
            for (int mf = 0; mf < 2; mf++) {
                uint32_t achunk = (uint32_t)((((kk * 2 + c2) ^ swA)) << 4);
                uint32_t aaddr = st + aRowByte + (uint32_t)(mf * 1024) + achunk;
                ldmat4(ah[mf], aaddr);
                ldmat4(al[mf], aaddr + ASZ);
            }
            const uint32_t bk = st + 2u * ASZ + (uint32_t)(kk * 16 * 256) + bRowByte;
#pragma unroll
            for (int j = 0; j < 4; j++) {
                uint32_t bh[4], bl[4];
                uint32_t bchunk = (uint32_t)(((warp_n * 8 + c2 + j * 2) ^ lrow) << 4);
                ldmat4t(bh, bk + bchunk);
                ldmat4t(bl, bk + bchunk + 8192u);
#pragma unroll
                for (int h = 0; h < 2; h++)
#pragma unroll
                    for (int mf = 0; mf < 2; mf++)
                        mma16816(acc[mf * 8 + j * 2 + h], ah[mf], &bh[h * 2]);
#pragma unroll
                for (int h = 0; h < 2; h++)
#pragma unroll
                    for (int mf = 0; mf < 2; mf++)
                        mma16816(acc[mf * 8 + j * 2 + h], ah[mf], &bl[h * 2]);
#pragma unroll
                for (int h = 0; h < 2; h++)
#pragma unroll
                    for (int mf = 0; mf < 2; mf++)
                        mma16816(acc[mf * 8 + j * 2 + h], al[mf], &bh[h * 2]);
            }
        }
    }

    const int ra = lane >> 2, ka = lane & 3;
    const int colBase = bn + warp_n * 64;

    if (CMODE == 3 && colBase < 2048) {
#pragma unroll
        for (int mf = 0; mf < 2; mf++)
#pragma unroll
            for (int hh = 0; hh < 2; hh++) {
                int gr = bm + warp_m * 32 + mf * 16 + ra + hh * 8;
                if (gr >= M) continue;
                const float* cb = cosb + (size_t)gr * 64;
                const float* sn = sinb + (size_t)gr * 64;
#pragma unroll
                for (int nf = 0; nf < 4; nf++) {
                    int d = nf * 8 + ka * 2;
                    float a0 = acc[mf * 8 + nf][hh * 2];
                    float a1 = acc[mf * 8 + nf][hh * 2 + 1];
                    float b0 = acc[mf * 8 + nf + 4][hh * 2];
                    float b1 = acc[mf * 8 + nf + 4][hh * 2 + 1];
                    float o0 = a0 * cb[d]     - b0 * sn[d];
                    float o1 = a1 * cb[d + 1] - b1 * sn[d + 1];
                    float p0 = b0 * cb[d + 32] + a0 * sn[d + 32];
                    float p1 = b1 * cb[d + 33] + a1 * sn[d + 33];
                    *(float2*)&C[(size_t)gr * N + colBase + d]      = make_float2(o0, o1);
                    *(float2*)&C[(size_t)gr * N + colBase + d + 32] = make_float2(p0, p1);
                }
            }
        return;
    }

#pragma unroll
    for (int mf = 0; mf < 2; mf++)
#pragma unroll
        for (int nf = 0; nf < 8; nf++) {
            const float* c = acc[mf * 8 + nf];
            int col = colBase + nf * 8 + ka * 2;
#pragma unroll
            for (int h = 0; h < 2; h++) {
                int gr = bm + warp_m * 32 + mf * 16 + ra + h * 8;
                if (gr >= M) continue;
                float v0 = c[h * 2], v1 = c[h * 2 + 1];
                if (CMODE == 0 || CMODE == 3) {
                    *(float2*)&C[(size_t)gr * N + col] = make_float2(v0, v1);
                } else {
                    int cr = (CMODE == 1) ? ((gr >> 6) * 65 + 1 + (gr & 63)) : gr;
                    st_bf16pair(Chi, Clo, (size_t)cr * N + col, v0, v1);
                }
            }
        }
}

#define DSMEM64  73728

// ---------------------------------------------------------------------------
// comp GEMM v5: fx = x.reshape(32,65536) @ W_comp, split-K.
// W_comp: raw fp32, 3-stage cp.async ring (16KB/stage), converted to bf16
// hi/lo fragment tiles in smem each iteration (double-buffered).
// x: bf16 hi/lo cp.async'd directly into padded fragment layout (3-stage).
// 2 syncs/iter; loads depth-2 asynchronous; term-major mma.
// Dynamic smem layout (bytes):
//   Wf32 @ 0      : 3 * 16384
//   Ahi  @ 49152  : 3 * 2560   (32 rows x 80B, same layout as round 9)
//   Alo  @ 56832  : 3 * 2560
//   Bhi  @ 64512  : 2 * 8704   (32 rows x 272B, same layout as round 9)
//   Blo  @ 81920  : 2 * 8704
// ---------------------------------------------------------------------------
#define CMP_WF32  0u
#define CMP_AHI   49152u
#define CMP_ALO   56832u
#define CMP_BHI   64512u
#define CMP_BLO   81920u
#define CMP_SMEM  99328

__global__ __launch_bounds__(256, 2)
void comp_kernel(const bf16* __restrict__ xhi, const bf16* __restrict__ xlo,
                 const float* __restrict__ Wc, float* __restrict__ fxpart)
{
    extern __shared__ char dsm[];
    const uint32_t sb = smem_u32(dsm);
    const int tid = threadIdx.x, lane = tid & 31, warp = tid >> 5;
    const int bn = blockIdx.x * 128;
    const int kb = blockIdx.y * 1024;

    // W cp.async: thread -> row = tid>>3 (0..31), chunks c = (tid&7)+8i, i<4
    const int wrow = tid >> 3, wch = tid & 7;
    // x cp.async: 128 chunks per buffer; tid<128 -> hi, else lo.
    const int xrow = (tid & 127) >> 2, xch = tid & 3;
    const bf16* xsrc = (tid < 128) ? xhi : xlo;
    const uint32_t xdstbase = (tid < 128) ? CMP_AHI : CMP_ALO;

    auto issue = [&](int it) {
        const int k0 = kb + it * 32;
        const uint32_t s3 = (uint32_t)(it % 3);
        const uint32_t wst = sb + CMP_WF32 + s3 * 16384u;
        const float* wsrc_row = Wc + (size_t)(k0 + wrow) * 1024 + bn;
#pragma unroll
        for (int i = 0; i < 4; i++) {
            int c = wch + 8 * i;
            cp16(wst + (uint32_t)(wrow * 512 + c * 16), wsrc_row + c * 4);
        }
        cp16(sb + xdstbase + s3 * 2560u + (uint32_t)(xrow * 80 + xch * 16),
             xsrc + (size_t)xrow * 65536 + k0 + xch * 8);
        asm volatile("cp.async.commit_group;\n" ::: "memory");
    };

    float acc[2][2][4];
#pragma unroll
    for (int i = 0; i < 2; i++)
#pragma unroll
        for (int j = 0; j < 2; j++)
#pragma unroll
            for (int q = 0; q < 4; q++) acc[i][j][q] = 0.f;

    const int quad = lane >> 3, lrow = lane & 7;
    const uint32_t a_off = (uint32_t)(((quad & 1) * 8 + lrow) * 80 + (quad >> 1) * 16);
    const uint32_t b_off = (uint32_t)(((quad & 1) * 8 + lrow) * 272 + (warp * 16 + (quad >> 1) * 8) * 2);

    issue(0);
    issue(1);

    for (int it = 0; it < 32; it++) {
        if (it < 30)
            asm volatile("cp.async.wait_group 1;\n" ::: "memory");
        else
            asm volatile("cp.async.wait_group 0;\n" ::: "memory");
        __syncthreads();                 // stage it%3 ready; issue-target WAR safe
        if (it + 2 < 32) issue(it + 2);

        // ---- convert W fp32 stage -> bf16 hi/lo tiles [it&1] ----
        const int s2 = it & 1;
        const char* wbase = dsm + CMP_WF32 + (uint32_t)(it % 3) * 16384u + wrow * 512;
        char* bhrow = dsm + CMP_BHI + (uint32_t)s2 * 8704u + wrow * 272;
        char* blrow = dsm + CMP_BLO + (uint32_t)s2 * 8704u + wrow * 272;
#pragma unroll
        for (int i = 0; i < 4; i++) {
            int c = wch + 8 * i;
            float4 v = *(const float4*)(wbase + c * 16);
            uint2 uh, ul;
            split2(v.x, v.y, uh.x, ul.x);
            split2(v.z, v.w, uh.y, ul.y);
            *(uint2*)(bhrow + c * 8) = uh;
            *(uint2*)(blrow + c * 8) = ul;
        }
        __syncthreads();                 // bf16 tiles ready for mma

        const uint32_t as = sb + CMP_AHI + (uint32_t)(it % 3) * 2560u;
        const uint32_t ls = sb + CMP_ALO + (uint32_t)(it % 3) * 2560u;
        const uint32_t bs = sb + CMP_BHI + (uint32_t)s2 * 8704u;
        const uint32_t cs = sb + CMP_BLO + (uint32_t)s2 * 8704u;
#pragma unroll
        for (int kk = 0; kk < 2; kk++) {
            uint32_t ah[2][4], al[2][4], bh[4], bl[4];
#pragma unroll
            for (int mf = 0; mf < 2; mf++) {
                ldmat4(ah[mf], as + mf * 1280u + a_off + kk * 32u);
                ldmat4(al[mf], ls + mf * 1280u + a_off + kk * 32u);
            }
            ldmat4t(bh, bs + b_off + kk * 4352u);
            ldmat4t(bl, cs + b_off + kk * 4352u);
#pragma unroll
            for (int nf = 0; nf < 2; nf++)
#pragma unroll
                for (int mf = 0; mf < 2; mf++)
                    mma16816(acc[mf][nf], ah[mf], &bh[nf * 2]);
#pragma unroll
            for (int nf = 0; nf < 2; nf++)
#pragma unroll
                for (int mf = 0; mf < 2; mf++)
                    mma16816(acc[mf][nf], ah[mf], &bl[nf * 2]);
#pragma unroll
            for (int nf = 0; nf < 2; nf++)
#pragma unroll
                for (int mf = 0; mf < 2; mf++)
                    mma16816(acc[mf][nf], al[mf], &bh[nf * 2]);
        }
    }

    const int ra = lane >> 2, ka = lane & 3;
#pragma unroll
    for (int mf = 0; mf < 2; mf++)
#pragma unroll
        for (int nf = 0; nf < 2; nf++)
#pragma unroll
            for (int h = 0; h < 2; h++) {
                int row = mf * 16 + ra + h * 8;
                int col = bn + warp * 16 + nf * 8 + ka * 2;
                *(float2*)&fxpart[(size_t)(blockIdx.y * 32 + row) * 1024 + col] =
                    make_float2(acc[mf][nf][h * 2], acc[mf][nf][h * 2 + 1]);
            }
}

// reduce partials (+bias / dummy) -> bf16 hi/lo anchor rows of h
__global__ void fx_reduce(const float* __restrict__ fxpart,
                          const float* __restrict__ dummy,
                          const float* __restrict__ bias,
                          bf16* __restrict__ hhi, bf16* __restrict__ hlo)
{
    int col = blockIdx.x * 128 + threadIdx.x;
    int c = blockIdx.y;
    float v;
    if (c == 0) {
        v = dummy[col];
    } else {
        int m = c - 1;
        float s = bias[col];
#pragma unroll 8
        for (int sl = 0; sl < CSLICES; sl++)
            s += fxpart[(size_t)(sl * 32 + m) * 1024 + col];
        v = s;
    }
    int hrow = (c < 32) ? c * 65 : 2080;
    bf16 h = __float2bfloat16(v);
    hhi[(size_t)hrow * CATD + col] = h;
    hlo[(size_t)hrow * CATD + col] = __float2bfloat16(v - __bfloat162float(h));
}

// ---------------------------------------------------------------------------
// Sparse CAT attention: K/V staged in smem, key-per-lane scores.
// ---------------------------------------------------------------------------
#define KPAD 68
#define ATTN_SMEM ((97 * KPAD * 2 + 8 * 64 + 8 * 100) * 4)

__global__ __launch_bounds__(256)
void attn_kernel(const float* __restrict__ qkv,
                 bf16* __restrict__ yhi, bf16* __restrict__ ylo)
{
    extern __shared__ float dyn[];
    float* sK = dyn;
    float* sV = sK + 97 * KPAD;
    float* sq = sV + 97 * KPAD;
    float* sp = sq + 8 * 64;

    const int cq = blockIdx.x;
    const int head = blockIdx.y;
    const int tid = threadIdx.x;
    const int warp = tid >> 5, lane = tid & 31;
    const int cnt = (cq == 32) ? 1 : 65;
    const int total = cq + cnt;

    for (int idx = tid; idx < total * 16; idx += 256) {
        int kk = idx >> 4, seg = idx & 15;
        int kp = (kk < cq) ? kk * 65 : cq * 65 + (kk - cq);
        const float* base = qkv + (size_t)kp * 3072 + head * 64 + seg * 4;
        float4 kv = *(const float4*)(base + 1024);
        float4 vv = *(const float4*)(base + 2048);
        *(float4*)&sK[kk * KPAD + seg * 4] = kv;
        *(float4*)&sV[kk * KPAD + seg * 4] = vv;
    }
    __syncthreads();

    for (int j = warp; j < cnt; j += 8) {
        const int p = cq * 65 + j;
        const int nk = cq + j + 1;

        float2 q2 = *(const float2*)(qkv + (size_t)p * 3072 + head * 64 + 2 * lane);
        sq[warp * 64 + 2 * lane]     = q2.x;
        sq[warp * 64 + 2 * lane + 1] = q2.y;
        __syncwarp();

        float mx = -1e30f;
        for (int kb2 = 0; kb2 < nk; kb2 += 32) {
            int kk = kb2 + lane;
            float s = -1e30f;
            if (kk < nk) {
                float a = 0.f;
#pragma unroll
                for (int d4 = 0; d4 < 16; d4++) {
                    float4 qv = *(const float4*)&sq[warp * 64 + d4 * 4];
                    float4 kv = *(const float4*)&sK[kk * KPAD + d4 * 4];
                    a += qv.x * kv.x + qv.y * kv.y + qv.z * kv.z + qv.w * kv.w;
                }
                s = a * 0.125f;
                sp[warp * 100 + kk] = s;
            }
            mx = fmaxf(mx, s);
        }
        mx = fmaxf(mx, __shfl_xor_sync(0xffffffffu, mx, 16));
        mx = fmaxf(mx, __shfl_xor_sync(0xffffffffu, mx, 8));
        mx = fmaxf(mx, __shfl_xor_sync(0xffffffffu, mx, 4));
        mx = fmaxf(mx, __shfl_xor_sync(0xffffffffu, mx, 2));
        mx = fmaxf(mx, __shfl_xor_sync(0xffffffffu, mx, 1));
        __syncwarp();

        float sum = 0.f;
        for (int kk = lane; kk < nk; kk += 32) {
            float e = __expf(sp[warp * 100 + kk] - mx);
            sp[warp * 100 + kk] = e;
            sum += e;
        }
        sum += __shfl_xor_sync(0xffffffffu, sum, 16);
        sum += __shfl_xor_sync(0xffffffffu, sum, 8);
        sum += __shfl_xor_sync(0xffffffffu, sum, 4);
        sum += __shfl_xor_sync(0xffffffffu, sum, 2);
        sum += __shfl_xor_sync(0xffffffffu, sum, 1);
        __syncwarp();
        float inv = 1.f / sum;

        float2 acc = make_float2(0.f, 0.f);
        for (int kk = 0; kk < nk; kk++) {
            float pr = sp[warp * 100 + kk];
            float2 v2 = *(const float2*)&sV[kk * KPAD + 2 * lane];
            acc.x += pr * v2.x;
            acc.y += pr * v2.y;
        }
        st_bf16pair(yhi, ylo, (size_t)p * CATD + head * 64 + 2 * lane,
                    acc.x * inv, acc.y * inv);
        __syncwarp();
    }
}

// ---------------------------------------------------------------------------
extern "C" void kernel_launch(void* const* d_in, const int* in_sizes, int n_in,
                              void* d_out, int out_size)
{
    const float* x        = (const float*)d_in[0];
    const float* W_expand = (const float*)d_in[1];
    const float* W_comp   = (const float*)d_in[2];
    const float* b_comp   = (const float*)d_in[3];
    const float* dummy_fx = (const float*)d_in[4];
    const float* W_qkv    = (const float*)d_in[5];
    const float* W_o      = (const float*)d_in[6];
    const float* W_final  = (const float*)d_in[7];
    const float* cosb     = (const float*)d_in[8];
    const float* sinb     = (const float*)d_in[9];
    float* out = (float*)d_out;

    float *fxpart, *qkv;
    bf16 *xhi, *xlo, *hhi, *hlo, *yhi, *ylo, *y2hi, *y2lo;
    bf16 *wexphi, *wexplo, *wqkvhi, *wqkvlo, *wohi, *wolo, *wfinhi, *wfinlo;
    cudaGetSymbolAddress((void**)&fxpart, g_fxpart);
    cudaGetSymbolAddress((void**)&qkv,    g_qkv);
    cudaGetSymbolAddress((void**)&xhi,    g_xhi);
    cudaGetSymbolAddress((void**)&xlo,    g_xlo);
    cudaGetSymbolAddress((void**)&hhi,    g_hhi);
    cudaGetSymbolAddress((void**)&hlo,    g_hlo);
    cudaGetSymbolAddress((void**)&yhi,    g_yhi);
    cudaGetSymbolAddress((void**)&ylo,    g_ylo);
    cudaGetSymbolAddress((void**)&y2hi,   g_y2hi);
    cudaGetSymbolAddress((void**)&y2lo,   g_y2lo);
    cudaGetSymbolAddress((void**)&wexphi, g_wexphi);
    cudaGetSymbolAddress((void**)&wexplo, g_wexplo);
    cudaGetSymbolAddress((void**)&wqkvhi, g_wqkvhi);
    cudaGetSymbolAddress((void**)&wqkvlo, g_wqkvlo);
    cudaGetSymbolAddress((void**)&wohi,   g_wohi);
    cudaGetSymbolAddress((void**)&wolo,   g_wolo);
    cudaGetSymbolAddress((void**)&wfinhi, g_wfinhi);
    cudaGetSymbolAddress((void**)&wfinlo, g_wfinlo);

    cudaFuncSetAttribute((const void*)mma_gemm<0, 1, 64>, cudaFuncAttributeMaxDynamicSharedMemorySize, DSMEM64);
    cudaFuncSetAttribute((const void*)mma_gemm<0, 3, 64>, cudaFuncAttributeMaxDynamicSharedMemorySize, DSMEM64);
    cudaFuncSetAttribute((const void*)mma_gemm<0, 2, 64>, cudaFuncAttributeMaxDynamicSharedMemorySize, DSMEM64);
    cudaFuncSetAttribute((const void*)mma_gemm<1, 0, 64>, cudaFuncAttributeMaxDynamicSharedMemorySize, DSMEM64);
    cudaFuncSetAttribute(comp_kernel, cudaFuncAttributeMaxDynamicSharedMemorySize, CMP_SMEM);
    cudaFuncSetAttribute(attn_kernel, cudaFuncAttributeMaxDynamicSharedMemorySize, ATTN_SMEM);

    // launch 0: all fp32 -> bf16 hi/lo conversions in one kernel
    cvt_all<<<4096, 256>>>(x,        xhi,    xlo,
                           W_expand, wexphi, wexplo,
                           W_qkv,    wqkvhi, wqkvlo,
                           W_o,      wohi,   wolo,
                           W_final,  wfinhi, wfinlo);

    // launch 1: fx partials (cp.async-pipelined tensor-core split-K)
    comp_kernel<<<dim3(8, CSLICES), 256, CMP_SMEM>>>(xhi, xlo, W_comp, fxpart);

    // launch 2: reduce partials -> bf16 anchor rows of h
    fx_reduce<<<dim3(8, 33), 128>>>(fxpart, dummy_fx, b_comp, hhi, hlo);

    // launch 3: xe = x @ W_expand -> scattered bf16 rows of h
    mma_gemm<0, 1, 64><<<dim3(8, 32), 128, DSMEM64>>>(xhi, xlo, wexphi, wexplo,
                                                      nullptr, hhi, hlo, nullptr, nullptr,
                                                      2048, 1024, 1024);

    // launch 4: qkv = h @ W_qkv (fp32 out, RoPE fused for q/k)
    mma_gemm<0, 3, 64><<<dim3(24, 33), 128, DSMEM64>>>(hhi, hlo, wqkvhi, wqkvlo,
                                                       qkv, nullptr, nullptr, cosb, sinb,
                                                       S_LEN, 3072, 1024);

    // launch 5: sparse CAT attention -> bf16 y
    attn_kernel<<<dim3(33, 16), 256, ATTN_SMEM>>>(qkv, yhi, ylo);

    // y2 = y @ W_o (bf16 out)
    mma_gemm<0, 2, 64><<<dim3(8, 33), 128, DSMEM64>>>(yhi, ylo, wohi, wolo,
                                                      nullptr, y2hi, y2lo, nullptr, nullptr,
                                                      S_LEN, 1024, 1024);

    // out = gather(y2) @ W_final (fp32 out)
    mma_gemm<1, 0, 64><<<dim3(8, 32), 128, DSMEM64>>>(y2hi, y2lo, wfinhi, wfinlo,
                                                      out, nullptr, nullptr, nullptr, nullptr,
                                                      2048, 1024, 1024);
}

// round 13
// speedup vs baseline: 1.2730x; 1.0249x over previous
#include <cuda_runtime.h>
#include <cuda_bf16.h>
#include <math.h>
#include <stdint.h>

// ---------------------------------------------------------------------------
// CAT_Attention (B=1, BLOCK=2048, CHUNK=64, DIM=1024, CAT=1024, NH=16, HD=64)
// S = 2081, W = 65, NC = 32
// Round 13: dense engine v4 — 64x64 warp tiles (4 warps per 128x128 CTA),
// cutting ldmatrix traffic per mma by 33%. comp v5 / attn / cvt unchanged.
// ---------------------------------------------------------------------------

#define S_LEN   2081
#define CATD    1024
#define NHEAD   16
#define CSLICES 64

typedef __nv_bfloat16 bf16;
typedef __nv_bfloat162 bf162;

// -------------------- scratch (device globals; no allocs) -------------------
__device__ float g_fxpart[CSLICES * 32 * 1024];
__device__ float g_qkv [S_LEN * 3 * CATD];
__device__ bf16  g_xhi[2048 * 1024],  g_xlo[2048 * 1024];
__device__ bf16  g_hhi[S_LEN * 1024], g_hlo[S_LEN * 1024];
__device__ bf16  g_yhi[S_LEN * 1024], g_ylo[S_LEN * 1024];
__device__ bf16  g_y2hi[S_LEN * 1024], g_y2lo[S_LEN * 1024];
__device__ bf16  g_wexphi[1024 * 1024], g_wexplo[1024 * 1024];
__device__ bf16  g_wqkvhi[1024 * 3072], g_wqkvlo[1024 * 3072];
__device__ bf16  g_wohi[1024 * 1024],   g_wolo[1024 * 1024];
__device__ bf16  g_wfinhi[1024 * 1024], g_wfinlo[1024 * 1024];

// -------------------- row maps ---------------------------------------------
__device__ __forceinline__ int amap_final(int r) {
    if (r < 63)    return r + 1;
    if (r == 2047) return 2080;
    int u = r - 63;
    return 65 + u + (u >> 6);
}

// -------------------- helpers ----------------------------------------------
__device__ __forceinline__ uint32_t smem_u32(const void* p) {
    return (uint32_t)__cvta_generic_to_shared(p);
}

__device__ __forceinline__ void cp16(uint32_t dst, const void* src) {
    asm volatile("cp.async.cg.shared.global [%0], [%1], 16;\n" :: "r"(dst), "l"(src));
}

__device__ __forceinline__ void mma16816(float* c, const uint32_t* a, const uint32_t* b) {
    asm volatile(
        "mma.sync.aligned.m16n8k16.row.col.f32.bf16.bf16.f32 "
        "{%0,%1,%2,%3}, {%4,%5,%6,%7}, {%8,%9}, {%0,%1,%2,%3};"
        : "+f"(c[0]), "+f"(c[1]), "+f"(c[2]), "+f"(c[3])
        : "r"(a[0]), "r"(a[1]), "r"(a[2]), "r"(a[3]), "r"(b[0]), "r"(b[1]));
}

__device__ __forceinline__ void ldmat4(uint32_t* r, uint32_t addr) {
    asm volatile(
        "ldmatrix.sync.aligned.m8n8.x4.shared.b16 {%0,%1,%2,%3}, [%4];"
        : "=r"(r[0]), "=r"(r[1]), "=r"(r[2]), "=r"(r[3]) : "r"(addr));
}

__device__ __forceinline__ void ldmat4t(uint32_t* r, uint32_t addr) {
    asm volatile(
        "ldmatrix.sync.aligned.m8n8.x4.trans.shared.b16 {%0,%1,%2,%3}, [%4];"
        : "=r"(r[0]), "=r"(r[1]), "=r"(r[2]), "=r"(r[3]) : "r"(addr));
}

__device__ __forceinline__ void split2(float a, float b, uint32_t& hi, uint32_t& lo) {
    bf16 h0 = __float2bfloat16(a), h1 = __float2bfloat16(b);
    bf16 l0 = __float2bfloat16(a - __bfloat162float(h0));
    bf16 l1 = __float2bfloat16(b - __bfloat162float(h1));
    bf162 hh = __halves2bfloat162(h0, h1), ll = __halves2bfloat162(l0, l1);
    hi = *(uint32_t*)&hh; lo = *(uint32_t*)&ll;
}

__device__ __forceinline__ void st_bf16pair(bf16* hi, bf16* lo, size_t idx,
                                            float v0, float v1) {
    uint32_t h, l;
    split2(v0, v1, h, l);
    *(uint32_t*)(hi + idx) = h;
    *(uint32_t*)(lo + idx) = l;
}

// ---------------------------------------------------------------------------
// merged convert: all 5 tensors in ONE launch; 2 float4 per thread.
// ---------------------------------------------------------------------------
__global__ __launch_bounds__(256)
void cvt_all(const float* __restrict__ s0, bf16* __restrict__ h0, bf16* __restrict__ l0,
             const float* __restrict__ s1, bf16* __restrict__ h1, bf16* __restrict__ l1,
             const float* __restrict__ s2, bf16* __restrict__ h2, bf16* __restrict__ l2,
             const float* __restrict__ s3, bf16* __restrict__ h3, bf16* __restrict__ l3,
             const float* __restrict__ s4, bf16* __restrict__ h4, bf16* __restrict__ l4)
{
    int b = blockIdx.x;
    const float* src; bf16 *hi, *lo; int base;
    if (b < 1024)      { src = s0; hi = h0; lo = l0; base = b; }
    else if (b < 1536) { src = s1; hi = h1; lo = l1; base = b - 1024; }
    else if (b < 3072) { src = s2; hi = h2; lo = l2; base = b - 1536; }
    else if (b < 3584) { src = s3; hi = h3; lo = l3; base = b - 3072; }
    else               { src = s4; hi = h4; lo = l4; base = b - 3584; }

    int i0 = base * 512 + threadIdx.x;
#pragma unroll
    for (int p = 0; p < 2; p++) {
        int i = i0 + p * 256;
        float4 v = ((const float4*)src)[i];
        uint2 uh, ul;
        split2(v.x, v.y, uh.x, ul.x);
        split2(v.z, v.w, uh.y, ul.y);
        *(uint2*)(hi + 4 * (size_t)i) = uh;
        *(uint2*)(lo + 4 * (size_t)i) = ul;
    }
}

// ---------------------------------------------------------------------------
// GEMM engine v4: CTA tile 128x128, 4 warps (2x2), warp tile 64x64.
// 128 threads. XOR-swizzled smem, 3-stage cp.async, 1 sync/iter, term-major.
// Stage: Ahi@0 Alo@8192 Bhi@16384 Blo@24576, 32KB/stage, 3 stages = 96KB.
// AMODE: 0 identity, 1 gather amap_final.
// CMODE: 0 fp32 C, 1 bf16 scatter->h, 2 bf16 identity, 3 fp32 + fused RoPE.
// ---------------------------------------------------------------------------
#define STAGE_SZ 32768u
#define DSMEM    98304

template<int AMODE, int CMODE>
__global__ __launch_bounds__(128, 2)
void mma_gemm(const bf16* __restrict__ Agh, const bf16* __restrict__ Agl,
              const bf16* __restrict__ Bgh, const bf16* __restrict__ Bgl,
              float* __restrict__ C, bf16* __restrict__ Chi, bf16* __restrict__ Clo,
              const float* __restrict__ cosb, const float* __restrict__ sinb,
              int M, int N, int K)
{
    extern __shared__ char dsm[];
    const uint32_t sb = smem_u32(dsm);
    const int tid = threadIdx.x, lane = tid & 31, wid = tid >> 5;
    const int warp_m = wid & 1, warp_n = wid >> 1;
    const int bm = blockIdx.y * 128, bn = blockIdx.x * 128;

    // ---- cp.async A: chunk c = tid + i*128 (i<4); row=c>>2, col=c&3 ----
    size_t aoff[4];
    uint32_t a_dst[4];
    {
        const int col = tid & 3;
        const int row0 = tid >> 2;
        const uint32_t aswz = (uint32_t)((col ^ ((row0 >> 1) & 3)) << 4);
#pragma unroll
        for (int i = 0; i < 4; i++) {
            int row = row0 + i * 32;
            int gr = bm + row;
            int r = (gr < M) ? gr : 0;
            if (AMODE == 1) r = amap_final(r);
            aoff[i] = (size_t)r * K + col * 8;
            a_dst[i] = (uint32_t)(row * 64) + aswz;   // (row>>1)&3 invariant mod 32
        }
    }
    // ---- cp.async B: chunk c = tid + i*128 (i<4); row=c>>4, col=c&15 ----
    const int bcol = tid & 15;
    const int brow0 = tid >> 4;                        // 0..7, +8 per i
    const size_t b_col = (size_t)bn + bcol * 8;
    const uint32_t bswz = (uint32_t)((bcol ^ (brow0 & 7)) << 4);
    uint32_t b_dst[4];
#pragma unroll
    for (int i = 0; i < 4; i++) b_dst[i] = (uint32_t)((brow0 + i * 8) * 256) + bswz;

    // ---- ldmatrix addressing ----
    const int quad = lane >> 3, lrow = lane & 7;
    const int c2 = quad >> 1;
    const int rowLocal = (quad & 1) * 8 + lrow;
    const int swA = (rowLocal >> 1) & 3;
    const uint32_t bRowByte = (uint32_t)(rowLocal * 256);

    float acc[32][4];
#pragma unroll
    for (int i = 0; i < 32; i++)
#pragma unroll
        for (int j = 0; j < 4; j++) acc[i][j] = 0.f;

    const int NIT = K >> 5;

    auto issue = [&](int it) {
        const int k0 = it << 5;
        const uint32_t st = sb + (uint32_t)(it % 3) * STAGE_SZ;
#pragma unroll
        for (int i = 0; i < 4; i++) {
            cp16(st + a_dst[i],         Agh + aoff[i] + k0);
            cp16(st + 8192u + a_dst[i], Agl + aoff[i] + k0);
        }
#pragma unroll
        for (int i = 0; i < 4; i++) {
            size_t src = (size_t)(k0 + brow0 + i * 8) * N + b_col;
            cp16(st + 16384u + b_dst[i], Bgh + src);
            cp16(st + 24576u + b_dst[i], Bgl + src);
        }
        asm volatile("cp.async.commit_group;\n" ::: "memory");
    };

    issue(0);
    issue(1);
    for (int it = 0; it < NIT; it++) {
        if (it + 1 < NIT)
            asm volatile("cp.async.wait_group 1;\n" ::: "memory");
        else
            asm volatile("cp.async.wait_group 0;\n" ::: "memory");
        __syncthreads();
        if (it + 2 < NIT) issue(it + 2);

        const uint32_t st = sb + (uint32_t)(it % 3) * STAGE_SZ;
#pragma unroll
        for (int kk = 0; kk < 2; kk++) {
            uint32_t ah[4][4], al[4][4];
            const uint32_t achunk = (uint32_t)((((kk * 2 + c2) ^ swA)) << 4);
#pragma unroll
            for (int mf = 0; mf < 4; mf++) {
                uint32_t aaddr = st +
                    (uint32_t)((warp_m * 64 + mf * 16 + rowLocal) * 64) + achunk;
                ldmat4(ah[mf], aaddr);
                ldmat4(al[mf], aaddr + 8192u);
            }
            const uint32_t bk = st + 16384u + (uint32_t)(kk * 16 * 256) + bRowByte;
#pragma unroll
            for (int j = 0; j < 4; j++) {
                uint32_t bh[4], bl[4];
                uint32_t bchunk = (uint32_t)(((warp_n * 8 + c2 + j * 2) ^ lrow) << 4);
                ldmat4t(bh, bk + bchunk);
                ldmat4t(bl, bk + bchunk + 8192u);
#pragma unroll
                for (int h = 0; h < 2; h++)
#pragma unroll
                    for (int mf = 0; mf < 4; mf++)
                        mma16816(acc[mf * 8 + j * 2 + h], ah[mf], &bh[h * 2]);
#pragma unroll
                for (int h = 0; h < 2; h++)
#pragma unroll
                    for (int mf = 0; mf < 4; mf++)
                        mma16816(acc[mf * 8 + j * 2 + h], ah[mf], &bl[h * 2]);
#pragma unroll
                for (int h = 0; h < 2; h++)
#pragma unroll
                    for (int mf = 0; mf < 4; mf++)
                        mma16816(acc[mf * 8 + j * 2 + h], al[mf], &bh[h * 2]);
            }
        }
    }

    // ---- epilogue ----
    const int ra = lane >> 2, ka = lane & 3;
    const int colBase = bn + warp_n * 64;

    if (CMODE == 3 && colBase < 2048) {
        // fused RoPE: pair (d, d+32) lives in acc[mf*8+nf] / acc[mf*8+nf+4]
#pragma unroll
        for (int mf = 0; mf < 4; mf++)
#pragma unroll
            for (int hh = 0; hh < 2; hh++) {
                int gr = bm + warp_m * 64 + mf * 16 + ra + hh * 8;
                if (gr >= M) continue;
                const float* cb = cosb + (size_t)gr * 64;
                const float* sn = sinb + (size_t)gr * 64;
#pragma unroll
                for (int nf = 0; nf < 4; nf++) {
                    int d = nf * 8 + ka * 2;
                    float a0 = acc[mf * 8 + nf][hh * 2];
                    float a1 = acc[mf * 8 + nf][hh * 2 + 1];
                    float b0 = acc[mf * 8 + nf + 4][hh * 2];
                    float b1 = acc[mf * 8 + nf + 4][hh * 2 + 1];
                    float o0 = a0 * cb[d]     - b0 * sn[d];
                    float o1 = a1 * cb[d + 1] - b1 * sn[d + 1];
                    float p0 = b0 * cb[d + 32] + a0 * sn[d + 32];
                    float p1 = b1 * cb[d + 33] + a1 * sn[d + 33];
                    *(float2*)&C[(size_t)gr * N + colBase + d]      = make_float2(o0, o1);
                    *(float2*)&C[(size_t)gr * N + colBase + d + 32] = make_float2(p0, p1);
                }
            }
        return;
    }

#pragma unroll
    for (int mf = 0; mf < 4; mf++)
#pragma unroll
        for (int nf = 0; nf < 8; nf++) {
            const float* c = acc[mf * 8 + nf];
            int col = colBase + nf * 8 + ka * 2;
#pragma unroll
            for (int h = 0; h < 2; h++) {
                int gr = bm + warp_m * 64 + mf * 16 + ra + h * 8;
                if (gr >= M) continue;
                float v0 = c[h * 2], v1 = c[h * 2 + 1];
                if (CMODE == 0 || CMODE == 3) {
                    *(float2*)&C[(size_t)gr * N + col] = make_float2(v0, v1);
                } else {
                    int cr = (CMODE == 1) ? ((gr >> 6) * 65 + 1 + (gr & 63)) : gr;
                    st_bf16pair(Chi, Clo, (size_t)cr * N + col, v0, v1);
                }
            }
        }
}

// ---------------------------------------------------------------------------
// comp GEMM v5 (round-12, measured win): fx = x @ W_comp, split-K.
// ---------------------------------------------------------------------------
#define CMP_WF32  0u
#define CMP_AHI   49152u
#define CMP_ALO   56832u
#define CMP_BHI   64512u
#define CMP_BLO   81920u
#define CMP_SMEM  99328

__global__ __launch_bounds__(256, 2)
void comp_kernel(const bf16* __restrict__ xhi, const bf16* __restrict__ xlo,
                 const float* __restrict__ Wc, float* __restrict__ fxpart)
{
    extern __shared__ char dsm[];
    const uint32_t sb = smem_u32(dsm);
    const int tid = threadIdx.x, lane = tid & 31, warp = tid >> 5;
    const int bn = blockIdx.x * 128;
    const int kb = blockIdx.y * 1024;

    const int wrow = tid >> 3, wch = tid & 7;
    const int xrow = (tid & 127) >> 2, xch = tid & 3;
    const bf16* xsrc = (tid < 128) ? xhi : xlo;
    const uint32_t xdstbase = (tid < 128) ? CMP_AHI : CMP_ALO;

    auto issue = [&](int it) {
        const int k0 = kb + it * 32;
        const uint32_t s3 = (uint32_t)(it % 3);
        const uint32_t wst = sb + CMP_WF32 + s3 * 16384u;
        const float* wsrc_row = Wc + (size_t)(k0 + wrow) * 1024 + bn;
#pragma unroll
        for (int i = 0; i < 4; i++) {
            int c = wch + 8 * i;
            cp16(wst + (uint32_t)(wrow * 512 + c * 16), wsrc_row + c * 4);
        }
        cp16(sb + xdstbase + s3 * 2560u + (uint32_t)(xrow * 80 + xch * 16),
             xsrc + (size_t)xrow * 65536 + k0 + xch * 8);
        asm volatile("cp.async.commit_group;\n" ::: "memory");
    };

    float acc[2][2][4];
#pragma unroll
    for (int i = 0; i < 2; i++)
#pragma unroll
        for (int j = 0; j < 2; j++)
#pragma unroll
            for (int q = 0; q < 4; q++) acc[i][j][q] = 0.f;

    const int quad = lane >> 3, lrow = lane & 7;
    const uint32_t a_off = (uint32_t)(((quad & 1) * 8 + lrow) * 80 + (quad >> 1) * 16);
    const uint32_t b_off = (uint32_t)(((quad & 1) * 8 + lrow) * 272 + (warp * 16 + (quad >> 1) * 8) * 2);

    issue(0);
    issue(1);

    for (int it = 0; it < 32; it++) {
        if (it < 30)
            asm volatile("cp.async.wait_group 1;\n" ::: "memory");
        else
            asm volatile("cp.async.wait_group 0;\n" ::: "memory");
        __syncthreads();
        if (it + 2 < 32) issue(it + 2);

        const int s2 = it & 1;
        const char* wbase = dsm + CMP_WF32 + (uint32_t)(it % 3) * 16384u + wrow * 512;
        char* bhrow = dsm + CMP_BHI + (uint32_t)s2 * 8704u + wrow * 272;
        char* blrow = dsm + CMP_BLO + (uint32_t)s2 * 8704u + wrow * 272;
#pragma unroll
        for (int i = 0; i < 4; i++) {
            int c = wch + 8 * i;
            float4 v = *(const float4*)(wbase + c * 16);
            uint2 uh, ul;
            split2(v.x, v.y, uh.x, ul.x);
            split2(v.z, v.w, uh.y, ul.y);
            *(uint2*)(bhrow + c * 8) = uh;
            *(uint2*)(blrow + c * 8) = ul;
        }
        __syncthreads();

        const uint32_t as = sb + CMP_AHI + (uint32_t)(it % 3) * 2560u;
        const uint32_t ls = sb + CMP_ALO + (uint32_t)(it % 3) * 2560u;
        const uint32_t bs = sb + CMP_BHI + (uint32_t)s2 * 8704u;
        const uint32_t cs = sb + CMP_BLO + (uint32_t)s2 * 8704u;
#pragma unroll
        for (int kk = 0; kk < 2; kk++) {
            uint32_t ah[2][4], al[2][4], bh[4], bl[4];
#pragma unroll
            for (int mf = 0; mf < 2; mf++) {
                ldmat4(ah[mf], as + mf * 1280u + a_off + kk * 32u);
                ldmat4(al[mf], ls + mf * 1280u + a_off + kk * 32u);
            }
            ldmat4t(bh, bs + b_off + kk * 4352u);
            ldmat4t(bl, cs + b_off + kk * 4352u);
#pragma unroll
            for (int nf = 0; nf < 2; nf++)
#pragma unroll
                for (int mf = 0; mf < 2; mf++)
                    mma16816(acc[mf][nf], ah[mf], &bh[nf * 2]);
#pragma unroll
            for (int nf = 0; nf < 2; nf++)
#pragma unroll
                for (int mf = 0; mf < 2; mf++)
                    mma16816(acc[mf][nf], ah[mf], &bl[nf * 2]);
#pragma unroll
            for (int nf = 0; nf < 2; nf++)
#pragma unroll
                for (int mf = 0; mf < 2; mf++)
                    mma16816(acc[mf][nf], al[mf], &bh[nf * 2]);
        }
    }

    const int ra = lane >> 2, ka = lane & 3;
#pragma unroll
    for (int mf = 0; mf < 2; mf++)
#pragma unroll
        for (int nf = 0; nf < 2; nf++)
#pragma unroll
            for (int h = 0; h < 2; h++) {
                int row = mf * 16 + ra + h * 8;
                int col = bn + warp * 16 + nf * 8 + ka * 2;
                *(float2*)&fxpart[(size_t)(blockIdx.y * 32 + row) * 1024 + col] =
                    make_float2(acc[mf][nf][h * 2], acc[mf][nf][h * 2 + 1]);
            }
}

// reduce partials (+bias / dummy) -> bf16 hi/lo anchor rows of h
__global__ void fx_reduce(const float* __restrict__ fxpart,
                          const float* __restrict__ dummy,
                          const float* __restrict__ bias,
                          bf16* __restrict__ hhi, bf16* __restrict__ hlo)
{
    int col = blockIdx.x * 128 + threadIdx.x;
    int c = blockIdx.y;
    float v;
    if (c == 0) {
        v = dummy[col];
    } else {
        int m = c - 1;
        float s = bias[col];
#pragma unroll 8
        for (int sl = 0; sl < CSLICES; sl++)
            s += fxpart[(size_t)(sl * 32 + m) * 1024 + col];
        v = s;
    }
    int hrow = (c < 32) ? c * 65 : 2080;
    bf16 h = __float2bfloat16(v);
    hhi[(size_t)hrow * CATD + col] = h;
    hlo[(size_t)hrow * CATD + col] = __float2bfloat16(v - __bfloat162float(h));
}

// ---------------------------------------------------------------------------
// Sparse CAT attention: K/V staged in smem, key-per-lane scores.
// ---------------------------------------------------------------------------
#define KPAD 68
#define ATTN_SMEM ((97 * KPAD * 2 + 8 * 64 + 8 * 100) * 4)

__global__ __launch_bounds__(256)
void attn_kernel(const float* __restrict__ qkv,
                 bf16* __restrict__ yhi, bf16* __restrict__ ylo)
{
    extern __shared__ float dyn[];
    float* sK = dyn;
    float* sV = sK + 97 * KPAD;
    float* sq = sV + 97 * KPAD;
    float* sp = sq + 8 * 64;

    const int cq = blockIdx.x;
    const int head = blockIdx.y;
    const int tid = threadIdx.x;
    const int warp = tid >> 5, lane = tid & 31;
    const int cnt = (cq == 32) ? 1 : 65;
    const int total = cq + cnt;

    for (int idx = tid; idx < total * 16; idx += 256) {
        int kk = idx >> 4, seg = idx & 15;
        int kp = (kk < cq) ? kk * 65 : cq * 65 + (kk - cq);
        const float* base = qkv + (size_t)kp * 3072 + head * 64 + seg * 4;
        float4 kv = *(const float4*)(base + 1024);
        float4 vv = *(const float4*)(base + 2048);
        *(float4*)&sK[kk * KPAD + seg * 4] = kv;
        *(float4*)&sV[kk * KPAD + seg * 4] = vv;
    }
    __syncthreads();

    for (int j = warp; j < cnt; j += 8) {
        const int p = cq * 65 + j;
        const int nk = cq + j + 1;

        float2 q2 = *(const float2*)(qkv + (size_t)p * 3072 + head * 64 + 2 * lane);
        sq[warp * 64 + 2 * lane]     = q2.x;
        sq[warp * 64 + 2 * lane + 1] = q2.y;
        __syncwarp();

        float mx = -1e30f;
        for (int kb2 = 0; kb2 < nk; kb2 += 32) {
            int kk = kb2 + lane;
            float s = -1e30f;
            if (kk < nk) {
                float a = 0.f;
#pragma unroll
                for (int d4 = 0; d4 < 16; d4++) {
                    float4 qv = *(const float4*)&sq[warp * 64 + d4 * 4];
                    float4 kv = *(const float4*)&sK[kk * KPAD + d4 * 4];
                    a += qv.x * kv.x + qv.y * kv.y + qv.z * kv.z + qv.w * kv.w;
                }
                s = a * 0.125f;
                sp[warp * 100 + kk] = s;
            }
            mx = fmaxf(mx, s);
        }
        mx = fmaxf(mx, __shfl_xor_sync(0xffffffffu, mx, 16));
        mx = fmaxf(mx, __shfl_xor_sync(0xffffffffu, mx, 8));
        mx = fmaxf(mx, __shfl_xor_sync(0xffffffffu, mx, 4));
        mx = fmaxf(mx, __shfl_xor_sync(0xffffffffu, mx, 2));
        mx = fmaxf(mx, __shfl_xor_sync(0xffffffffu, mx, 1));
        __syncwarp();

        float sum = 0.f;
        for (int kk = lane; kk < nk; kk += 32) {
            float e = __expf(sp[warp * 100 + kk] - mx);
            sp[warp * 100 + kk] = e;
            sum += e;
        }
        sum += __shfl_xor_sync(0xffffffffu, sum, 16);
        sum += __shfl_xor_sync(0xffffffffu, sum, 8);
        sum += __shfl_xor_sync(0xffffffffu, sum, 4);
        sum += __shfl_xor_sync(0xffffffffu, sum, 2);
        sum += __shfl_xor_sync(0xffffffffu, sum, 1);
        __syncwarp();
        float inv = 1.f / sum;

        float2 acc = make_float2(0.f, 0.f);
        for (int kk = 0; kk < nk; kk++) {
            float pr = sp[warp * 100 + kk];
            float2 v2 = *(const float2*)&sV[kk * KPAD + 2 * lane];
            acc.x += pr * v2.x;
            acc.y += pr * v2.y;
        }
        st_bf16pair(yhi, ylo, (size_t)p * CATD + head * 64 + 2 * lane,
                    acc.x * inv, acc.y * inv);
        __syncwarp();
    }
}

// ---------------------------------------------------------------------------
extern "C" void kernel_launch(void* const* d_in, const int* in_sizes, int n_in,
                              void* d_out, int out_size)
{
    const float* x        = (const float*)d_in[0];
    const float* W_expand = (const float*)d_in[1];
    const float* W_comp   = (const float*)d_in[2];
    const float* b_comp   = (const float*)d_in[3];
    const float* dummy_fx = (const float*)d_in[4];
    const float* W_qkv    = (const float*)d_in[5];
    const float* W_o      = (const float*)d_in[6];
    const float* W_final  = (const float*)d_in[7];
    const float* cosb     = (const float*)d_in[8];
    const float* sinb     = (const float*)d_in[9];
    float* out = (float*)d_out;

    float *fxpart, *qkv;
    bf16 *xhi, *xlo, *hhi, *hlo, *yhi, *ylo, *y2hi, *y2lo;
    bf16 *wexphi, *wexplo, *wqkvhi, *wqkvlo, *wohi, *wolo, *wfinhi, *wfinlo;
    cudaGetSymbolAddress((void**)&fxpart, g_fxpart);
    cudaGetSymbolAddress((void**)&qkv,    g_qkv);
    cudaGetSymbolAddress((void**)&xhi,    g_xhi);
    cudaGetSymbolAddress((void**)&xlo,    g_xlo);
    cudaGetSymbolAddress((void**)&hhi,    g_hhi);
    cudaGetSymbolAddress((void**)&hlo,    g_hlo);
    cudaGetSymbolAddress((void**)&yhi,    g_yhi);
    cudaGetSymbolAddress((void**)&ylo,    g_ylo);
    cudaGetSymbolAddress((void**)&y2hi,   g_y2hi);
    cudaGetSymbolAddress((void**)&y2lo,   g_y2lo);
    cudaGetSymbolAddress((void**)&wexphi, g_wexphi);
    cudaGetSymbolAddress((void**)&wexplo, g_wexplo);
    cudaGetSymbolAddress((void**)&wqkvhi, g_wqkvhi);
    cudaGetSymbolAddress((void**)&wqkvlo, g_wqkvlo);
    cudaGetSymbolAddress((void**)&wohi,   g_wohi);
    cudaGetSymbolAddress((void**)&wolo,   g_wolo);
    cudaGetSymbolAddress((void**)&wfinhi, g_wfinhi);
    cudaGetSymbolAddress((void**)&wfinlo, g_wfinlo);

    cudaFuncSetAttribute((const void*)mma_gemm<0, 1>, cudaFuncAttributeMaxDynamicSharedMemorySize, DSMEM);
    cudaFuncSetAttribute((const void*)mma_gemm<0, 3>, cudaFuncAttributeMaxDynamicSharedMemorySize, DSMEM);
    cudaFuncSetAttribute((const void*)mma_gemm<0, 2>, cudaFuncAttributeMaxDynamicSharedMemorySize, DSMEM);
    cudaFuncSetAttribute((const void*)mma_gemm<1, 0>, cudaFuncAttributeMaxDynamicSharedMemorySize, DSMEM);
    cudaFuncSetAttribute(comp_kernel, cudaFuncAttributeMaxDynamicSharedMemorySize, CMP_SMEM);
    cudaFuncSetAttribute(attn_kernel, cudaFuncAttributeMaxDynamicSharedMemorySize, ATTN_SMEM);

    // launch 0: all fp32 -> bf16 hi/lo conversions in one kernel
    cvt_all<<<4096, 256>>>(x,        xhi,    xlo,
                           W_expand, wexphi, wexplo,
                           W_qkv,    wqkvhi, wqkvlo,
                           W_o,      wohi,   wolo,
                           W_final,  wfinhi, wfinlo);

    // launch 1: fx partials (cp.async-pipelined tensor-core split-K)
    comp_kernel<<<dim3(8, CSLICES), 256, CMP_SMEM>>>(xhi, xlo, W_comp, fxpart);

    // launch 2: reduce partials -> bf16 anchor rows of h
    fx_reduce<<<dim3(8, 33), 128>>>(fxpart, dummy_fx, b_comp, hhi, hlo);

    // launch 3 (profile target): xe = x @ W_expand -> scattered bf16 rows of h
    mma_gemm<0, 1><<<dim3(8, 16), 128, DSMEM>>>(xhi, xlo, wexphi, wexplo,
                                                nullptr, hhi, hlo, nullptr, nullptr,
                                                2048, 1024, 1024);

    // launch 4: qkv = h @ W_qkv (fp32 out, RoPE fused for q/k)
    mma_gemm<0, 3><<<dim3(24, 17), 128, DSMEM>>>(hhi, hlo, wqkvhi, wqkvlo,
                                                 qkv, nullptr, nullptr, cosb, sinb,
                                                 S_LEN, 3072, 1024);

    // launch 5: sparse CAT attention -> bf16 y
    attn_kernel<<<dim3(33, 16), 256, ATTN_SMEM>>>(qkv, yhi, ylo);

    // y2 = y @ W_o (bf16 out)
    mma_gemm<0, 2><<<dim3(8, 17), 128, DSMEM>>>(yhi, ylo, wohi, wolo,
                                                nullptr, y2hi, y2lo, nullptr, nullptr,
                                                S_LEN, 1024, 1024);

    // out = gather(y2) @ W_final (fp32 out)
    mma_gemm<1, 0><<<dim3(8, 16), 128, DSMEM>>>(y2hi, y2lo, wfinhi, wfinlo,
                                                out, nullptr, nullptr, nullptr, nullptr,
                                                2048, 1024, 1024);
}